// round 7
// baseline (speedup 1.0000x reference)
#include <cuda_runtime.h>
#include <cuda_bf16.h>
#include <cuda_fp16.h>
#include <math.h>
#include <stdint.h>

// Problem dims
#define BATCH 64
#define PP    196
#define TT    30
#define VV    30000
#define NPAD  30080
#define KEXT  1536      // 3 x 512 (hi*hi + hi*lo + lo*hi)

// ---------------- device scratch ----------------
__device__ float g_h[BATCH * 512];
__device__ float g_c[BATCH * 512];
__device__ float g_hgate[BATCH * 512];
__device__ float g_x[BATCH * 1536];               // [emb | ctx | h]
__device__ float g_gates[BATCH * 2048];
__device__ float g_Wcat[1536 * 2048];
__device__ float g_bias4[2048];
__device__ float g_biasdb[1024];                  // [bd_att | b_beta]
__device__ float g_WdbT[1024 * 512];              // [Wd | W_beta]^T fp32
__device__ float g_H[TT * BATCH * 512];           // 1920 rows (1856 real)

__device__ __half2 g_ep2[12544 * 256];            // enc_proj half2
__device__ __half2 g_dp2[BATCH * 256];            // dec_proj half2
__device__ __half2 g_wf2[256];

__device__ __nv_bfloat16 g_Aext[12544 * KEXT];
__device__ __nv_bfloat16 g_Bext[NPAD * KEXT];
__device__ __nv_bfloat16 g_Wext[512 * KEXT];

__device__ __forceinline__ float sigf(float x) { return 1.f / (1.f + expf(-x)); }
__device__ __forceinline__ uint32_t smem_u32(const void* p) {
    uint32_t a;
    asm("{ .reg .u64 t; cvta.to.shared.u64 t, %1; cvt.u32.u64 %0, t; }" : "=r"(a) : "l"(p));
    return a;
}
__device__ __forceinline__ __half2 tanh2(__half2 v) {
    uint32_t u = *reinterpret_cast<uint32_t*>(&v), r;
    asm("tanh.approx.f16x2 %0, %1;" : "=r"(r) : "r"(u));
    return *reinterpret_cast<__half2*>(&r);
}

// ---------------- mma.sync bf16 GEMM ----------------
#define NSTAGE (KEXT / 64)   // 24

__device__ __forceinline__ void ldm4(uint32_t* r, uint32_t addr) {
    asm volatile("ldmatrix.sync.aligned.m8n8.x4.shared.b16 {%0,%1,%2,%3}, [%4];"
        : "=r"(r[0]), "=r"(r[1]), "=r"(r[2]), "=r"(r[3]) : "r"(addr));
}
__device__ __forceinline__ void mma16816(float* c, const uint32_t* a, uint32_t b0, uint32_t b1) {
    asm volatile("mma.sync.aligned.m16n8k16.row.col.f32.bf16.bf16.f32 "
        "{%0,%1,%2,%3}, {%4,%5,%6,%7}, {%8,%9}, {%0,%1,%2,%3};"
        : "+f"(c[0]), "+f"(c[1]), "+f"(c[2]), "+f"(c[3])
        : "r"(a[0]), "r"(a[1]), "r"(a[2]), "r"(a[3]), "r"(b0), "r"(b1));
}
#define CPA(saddr, gaddr) \
    asm volatile("cp.async.cg.shared.global [%0], [%1], 16;" :: "r"(saddr), "l"(gaddr))
#define CPA_COMMIT() asm volatile("cp.async.commit_group;")
#define CPA_WAIT0()  asm volatile("cp.async.wait_group 0;")

// EPI 0: enc_proj -> g_ep2 half2 (+bias). EPI 2: vocab scatter + bias.
template <int EPI>
__global__ void __launch_bounds__(256) mma_gemm(
    const __nv_bfloat16* __restrict__ Aext, const __nv_bfloat16* __restrict__ Bext,
    float* __restrict__ C, const float* __restrict__ bias,
    int Mreal, int Nreal, int mOff)
{
    extern __shared__ char sm[];
    const uint32_t sb = smem_u32(sm);
    const int tid = threadIdx.x;
    const int m0 = mOff + blockIdx.y * 128;
    const int n0 = blockIdx.x * 128;

    const __nv_bfloat16* Ag = Aext + (long)m0 * KEXT;
    const __nv_bfloat16* Bg = Bext + (long)n0 * KEXT;

    const int wid = tid >> 5, lane = tid & 31;
    const int wm = wid & 3, wn = wid >> 2;
    const int g = lane >> 3, r = lane & 7;
    const int lrow = (g & 1) * 8 + r;
    const uint32_t lkb = (g >> 1) * 16;
    const uint32_t xorp = (uint32_t)(r << 4);

    uint32_t aoff[2], boff[4];
#pragma unroll
    for (int mt = 0; mt < 2; mt++) aoff[mt] = (uint32_t)((wm * 32 + mt * 16 + lrow) * 128);
#pragma unroll
    for (int bt = 0; bt < 4; bt++) boff[bt] = (uint32_t)(16384 + (wn * 64 + bt * 16 + lrow) * 128);

    float acc[2][8][4];
#pragma unroll
    for (int i = 0; i < 2; i++)
#pragma unroll
        for (int j = 0; j < 8; j++)
#pragma unroll
            for (int q = 0; q < 4; q++) acc[i][j][q] = 0.f;

    {
#pragma unroll
        for (int i = 0; i < 4; i++) {
            int idx = i * 256 + tid;
            int row = idx >> 3, c = idx & 7;
            uint32_t so = (uint32_t)(row * 128 + ((c * 16) ^ ((row & 7) << 4)));
            CPA(sb + so, Ag + (long)row * KEXT + c * 8);
            CPA(sb + 16384 + so, Bg + (long)row * KEXT + c * 8);
        }
        CPA_COMMIT();
    }

    for (int s = 0; s < NSTAGE; s++) {
        CPA_WAIT0();
        __syncthreads();
        if (s + 1 < NSTAGE) {
            const uint32_t dstb = sb + ((s + 1) & 1) * 32768;
            const long kb = (long)(s + 1) * 64;
#pragma unroll
            for (int i = 0; i < 4; i++) {
                int idx = i * 256 + tid;
                int row = idx >> 3, c = idx & 7;
                uint32_t so = (uint32_t)(row * 128 + ((c * 16) ^ ((row & 7) << 4)));
                CPA(dstb + so, Ag + (long)row * KEXT + kb + c * 8);
                CPA(dstb + 16384 + so, Bg + (long)row * KEXT + kb + c * 8);
            }
            CPA_COMMIT();
        }

        const uint32_t sbase = sb + (s & 1) * 32768;
#pragma unroll
        for (int kk = 0; kk < 4; kk++) {
            const uint32_t kb = (uint32_t)(kk * 32 + lkb) ^ xorp;
            uint32_t a0[4], a1[4];
            ldm4(a0, sbase + aoff[0] + kb);
            ldm4(a1, sbase + aoff[1] + kb);
#pragma unroll
            for (int bt = 0; bt < 4; bt++) {
                uint32_t bm[4];
                ldm4(bm, sbase + boff[bt] + kb);
                mma16816(acc[0][2 * bt],     a0, bm[0], bm[2]);
                mma16816(acc[1][2 * bt],     a1, bm[0], bm[2]);
                mma16816(acc[0][2 * bt + 1], a0, bm[1], bm[3]);
                mma16816(acc[1][2 * bt + 1], a1, bm[1], bm[3]);
            }
        }
        __syncthreads();
    }

    const int crow0 = lane >> 2;
    const int ccol = (lane & 3) * 2;
#pragma unroll
    for (int mt = 0; mt < 2; mt++) {
#pragma unroll
        for (int h = 0; h < 2; h++) {
            const int m = m0 + wm * 32 + mt * 16 + crow0 + h * 8;
            if (EPI == 0) {
#pragma unroll
                for (int nt = 0; nt < 8; nt++) {
                    const int n = n0 + wn * 64 + nt * 8 + ccol;
                    float vx = acc[mt][nt][h * 2 + 0] + bias[n];
                    float vy = acc[mt][nt][h * 2 + 1] + bias[n + 1];
                    g_ep2[(long)m * 256 + (n >> 1)] = __floats2half2_rn(vx, vy);
                }
            } else {
                if (m < Mreal) {
                    int t = (m >> 6) + 1;
                    int b = m & 63;
                    float* crow = C + (long)b * (TT * VV) + (long)t * VV;
#pragma unroll
                    for (int nt = 0; nt < 8; nt++) {
                        const int n = n0 + wn * 64 + nt * 8 + ccol;
                        if (n < Nreal) {
                            float2 o;
                            o.x = acc[mt][nt][h * 2 + 0] + bias[n];
                            o.y = acc[mt][nt][h * 2 + 1] + bias[n + 1];
                            *reinterpret_cast<float2*>(crow + n) = o;
                        }
                    }
                }
            }
        }
    }
}

// ---------------- conversion kernels ----------------
__global__ void k_cvt_ext(const float* __restrict__ src, __nv_bfloat16* __restrict__ dst, int n) {
    int i = blockIdx.x * 256 + threadIdx.x;
    if (i < n) {
        int row = i >> 9, k = i & 511;
        float x = src[i];
        __nv_bfloat16 h = __float2bfloat16(x);
        __nv_bfloat16 l = __float2bfloat16(x - __bfloat162float(h));
        __nv_bfloat16* d = dst + (long)row * KEXT + k;
        d[0] = h; d[512] = h; d[1024] = l;
    }
}

__global__ void k_tsp_ext(const float* __restrict__ src, __nv_bfloat16* __restrict__ dst,
                          int N, int Npad) {
    __shared__ float t[32][33];
    int n0 = blockIdx.x * 32, k0 = blockIdx.y * 32;
    int tx = threadIdx.x, ty = threadIdx.y;
#pragma unroll
    for (int i = 0; i < 32; i += 8) {
        int k = k0 + ty + i, n = n0 + tx;
        t[ty + i][tx] = (n < N) ? src[(long)k * N + n] : 0.f;
    }
    __syncthreads();
#pragma unroll
    for (int i = 0; i < 32; i += 8) {
        int n = n0 + ty + i, k = k0 + tx;
        if (n < Npad) {
            float x = t[tx][ty + i];
            __nv_bfloat16 h = __float2bfloat16(x);
            __nv_bfloat16 l = __float2bfloat16(x - __bfloat162float(h));
            __nv_bfloat16* d = dst + (long)n * KEXT + k;
            d[0] = h; d[512] = l; d[1024] = h;
        }
    }
}

__global__ void k_tspf(const float* __restrict__ src, int off) {
    __shared__ float t[32][33];
    int n0 = blockIdx.x * 32, k0 = blockIdx.y * 32;
    int tx = threadIdx.x, ty = threadIdx.y;
#pragma unroll
    for (int i = 0; i < 32; i += 8)
        t[ty + i][tx] = src[(long)(k0 + ty + i) * 512 + n0 + tx];
    __syncthreads();
#pragma unroll
    for (int i = 0; i < 32; i += 8)
        g_WdbT[(long)(off + n0 + ty + i) * 512 + k0 + tx] = t[tx][ty + i];
}

// ---------------- prologue kernels ----------------
__global__ void k_zero_t0(float* __restrict__ out) {
    int idx = blockIdx.x * 256 + threadIdx.x;
    if (idx < BATCH * VV) {
        int b = idx / VV, v = idx - b * VV;
        out[(long)b * (TT * VV) + v] = 0.f;
    }
}

__global__ void k_init_hc(const float* __restrict__ pooled,
                          const float* __restrict__ Wh, const float* __restrict__ bh,
                          const float* __restrict__ Wc, const float* __restrict__ bc) {
    int b = blockIdx.y;
    int j = blockIdx.x * 256 + threadIdx.x;
    __shared__ float pr[512];
    pr[threadIdx.x] = pooled[b * 512 + threadIdx.x];
    pr[threadIdx.x + 256] = pooled[b * 512 + threadIdx.x + 256];
    __syncthreads();
    float a0 = 0, a1 = 0, a2 = 0, a3 = 0;
    const float* W = (j < 512) ? (Wh + j) : (Wc + j - 512);
    for (int k = 0; k < 512; k += 4) {
        a0 += pr[k] * W[k * 512];
        a1 += pr[k + 1] * W[(k + 1) * 512];
        a2 += pr[k + 2] * W[(k + 2) * 512];
        a3 += pr[k + 3] * W[(k + 3) * 512];
    }
    float s = (a0 + a1) + (a2 + a3);
    if (j < 512) g_h[b * 512 + j] = tanhf(s + bh[j]);
    else         g_c[b * 512 + (j - 512)] = tanhf(s + bc[j - 512]);
}

__global__ void k_wcat(const float* __restrict__ Wih, const float* __restrict__ Whh,
                       const float* __restrict__ bih, const float* __restrict__ bhh,
                       const float* __restrict__ bd, const float* __restrict__ bb,
                       const float* __restrict__ wf) {
    int idx = blockIdx.x * 256 + threadIdx.x;
    if (idx < 1536 * 2048) {
        int k = idx >> 11, n = idx & 2047;
        g_Wcat[idx] = (k < 1024) ? Wih[idx] : Whh[(k - 1024) * 2048 + n];
    }
    if (idx < 2048) g_bias4[idx] = bih[idx] + bhh[idx];
    if (idx < 1024) g_biasdb[idx] = (idx < 512) ? bd[idx] : bb[idx - 512];
    if (idx < 256)  g_wf2[idx] = __floats2half2_rn(wf[2 * idx], wf[2 * idx + 1]);
}

__global__ void k_prep0(const int* __restrict__ captions, const float* __restrict__ emb) {
    int idx = blockIdx.x * 256 + threadIdx.x;    // 32768
    int b = idx >> 9, d = idx & 511;
    int tok = captions[b * TT];
    g_x[b * 1536 + d] = emb[(long)tok * 512 + d];
    g_x[b * 1536 + 1024 + d] = g_h[idx];
    g_gates[b * 2048 + d]        = g_bias4[d];
    g_gates[b * 2048 + 512 + d]  = g_bias4[512 + d];
    g_gates[b * 2048 + 1024 + d] = g_bias4[1024 + d];
    g_gates[b * 2048 + 1536 + d] = g_bias4[1536 + d];
    g_H[1856 * 512 + idx] = 0.f;   // zero the padded H tail
}

// ---------------- per-step kernels ----------------
// P1: dec_proj + gate, warp-per-j GEMV (128 CTAs)
__global__ void __launch_bounds__(256) k_gemv() {
    const int wid = threadIdx.x >> 5, lane = threadIdx.x & 31;
    const int j = blockIdx.x * 8 + wid;   // 0..1023
    float wt[16];
    const float* wrow = g_WdbT + (long)j * 512;
#pragma unroll
    for (int i = 0; i < 16; i++) wt[i] = wrow[lane + i * 32];
    const float bias = g_biasdb[j];
#pragma unroll 2
    for (int b = 0; b < 64; b++) {
        const float* hb = g_h + b * 512;
        float acc = 0.f;
#pragma unroll
        for (int i = 0; i < 16; i++) acc += wt[i] * hb[lane + i * 32];
#pragma unroll
        for (int o = 16; o; o >>= 1) acc += __shfl_down_sync(0xffffffffu, acc, o);
        if (lane == 0) {
            float s = acc + bias;
            if (j < 512) reinterpret_cast<__half*>(g_dp2)[b * 512 + j] = __float2half(s);
            else         g_hgate[b * 512 + (j - 512)] = sigf(s);
        }
    }
}

// P2: scores + softmax + gated ctx (64 CTAs, one per batch)
__global__ void __launch_bounds__(256) k_attall(const float* __restrict__ feats) {
    const int b = blockIdx.x;
    const int tid = threadIdx.x;
    const int wid = tid >> 5, lane = tid & 31;
    __shared__ __half2 sdp[256], swf[256];
    __shared__ float sc[256], sred[256];
    sdp[tid] = g_dp2[b * 256 + tid];
    swf[tid] = g_wf2[tid];
    if (tid >= PP) sc[tid] = -1e30f;
    __syncthreads();
    for (int rr = 0; rr < 25; rr++) {
        int p = rr * 8 + wid;
        if (p < PP) {
            const __half2* ep = g_ep2 + (long)(b * PP + p) * 256;
            float accf = 0.f;
#pragma unroll
            for (int u = 0; u < 2; u++) {
                int i0 = u * 128 + lane * 4;
                uint4 ev = *reinterpret_cast<const uint4*>(ep + i0);
                const __half2* e2 = reinterpret_cast<const __half2*>(&ev);
#pragma unroll
                for (int jj = 0; jj < 4; jj += 2) {
                    __half2 t0 = tanh2(__hadd2(e2[jj],     sdp[i0 + jj]));
                    __half2 t1 = tanh2(__hadd2(e2[jj + 1], sdp[i0 + jj + 1]));
                    __half2 a2 = __hfma2(t1, swf[i0 + jj + 1], __hmul2(t0, swf[i0 + jj]));
                    float2 f = __half22float2(a2);
                    accf += f.x + f.y;
                }
            }
#pragma unroll
            for (int o = 16; o; o >>= 1) accf += __shfl_down_sync(0xffffffffu, accf, o);
            if (lane == 0) sc[p] = accf;
        }
    }
    __syncthreads();
    float v = sc[tid];
    sred[tid] = v;
    __syncthreads();
    for (int s = 128; s > 0; s >>= 1) {
        if (tid < s) sred[tid] = fmaxf(sred[tid], sred[tid + s]);
        __syncthreads();
    }
    float mx = sred[0];
    __syncthreads();
    float e = (tid < PP) ? expf(v - mx) : 0.f;
    sred[tid] = e;
    __syncthreads();
    for (int s = 128; s > 0; s >>= 1) {
        if (tid < s) sred[tid] += sred[tid + s];
        __syncthreads();
    }
    float inv = 1.f / sred[0];
    __syncthreads();
    sc[tid] = e * inv;
    __syncthreads();
    const float* fb = feats + (long)b * PP * 512;
#pragma unroll
    for (int half = 0; half < 2; half++) {
        int d = half * 256 + tid;
        float acc = 0.f;
        const float* fp = fb + d;
#pragma unroll 4
        for (int p = 0; p < PP; p++) acc += sc[p] * fp[p * 512];
        g_x[b * 1536 + 512 + d] = acc * g_hgate[b * 512 + d];
    }
}

// ---------------- packed f32x2 helpers + gates GEMM ----------------
__device__ __forceinline__ unsigned long long pack2(float x) {
    unsigned long long r;
    asm("mov.b64 %0, {%1, %1};" : "=l"(r) : "f"(x));
    return r;
}
__device__ __forceinline__ void fma2(unsigned long long& d, unsigned long long a, unsigned long long b) {
    asm("fma.rn.f32x2 %0, %1, %2, %0;" : "+l"(d) : "l"(a), "l"(b));
}
__device__ __forceinline__ float2 unpack2(unsigned long long v) {
    float2 r;
    asm("mov.b64 {%0, %1}, %2;" : "=f"(r.x), "=f"(r.y) : "l"(v));
    return r;
}

__global__ void __launch_bounds__(256) gemm_gates(
    const float* __restrict__ A, const float* __restrict__ B,
    float* __restrict__ C, int N, int K, int kLen)
{
    __shared__ float As[2][16][64];
    __shared__ float Bs[2][16][128];

    const int tid = threadIdx.x;
    const int n0 = blockIdx.x * 128;
    const int kStart = blockIdx.z * kLen;
    const int tn = (tid & 15) * 8;
    const int tm = (tid >> 4) * 4;
    const int am = tid >> 2, ak = (tid & 3) * 4;
    const int bk = tid >> 4, bn = (tid & 15) * 8;

    const float* Aptr = A + (long)am * K + kStart + ak;
    const float* Bptr = B + (long)(kStart + bk) * N + n0 + bn;

    unsigned long long acc[4][4];
#pragma unroll
    for (int i = 0; i < 4; i++) acc[i][0] = acc[i][1] = acc[i][2] = acc[i][3] = 0ull;

    const int nb = kLen / 16;
    float4 ar0, br0, br1;
    ar0 = *reinterpret_cast<const float4*>(Aptr);
    br0 = *reinterpret_cast<const float4*>(Bptr);
    br1 = *reinterpret_cast<const float4*>(Bptr + 4);
    As[0][ak + 0][am] = ar0.x; As[0][ak + 1][am] = ar0.y;
    As[0][ak + 2][am] = ar0.z; As[0][ak + 3][am] = ar0.w;
    *reinterpret_cast<float4*>(&Bs[0][bk][bn]) = br0;
    *reinterpret_cast<float4*>(&Bs[0][bk][bn + 4]) = br1;
    __syncthreads();

    for (int ib = 0; ib < nb; ib++) {
        const int cur = ib & 1;
        const bool more = (ib + 1) < nb;
        if (more) {
            ar0 = *reinterpret_cast<const float4*>(Aptr + (ib + 1) * 16);
            const float* bp = Bptr + (long)((ib + 1) * 16) * N;
            br0 = *reinterpret_cast<const float4*>(bp);
            br1 = *reinterpret_cast<const float4*>(bp + 4);
        }
#pragma unroll
        for (int kk = 0; kk < 16; kk++) {
            unsigned long long ad[4];
            float4 af = *reinterpret_cast<const float4*>(&As[cur][kk][tm]);
            ad[0] = pack2(af.x); ad[1] = pack2(af.y); ad[2] = pack2(af.z); ad[3] = pack2(af.w);
            ulonglong2 bv0 = *reinterpret_cast<const ulonglong2*>(&Bs[cur][kk][tn]);
            ulonglong2 bv1 = *reinterpret_cast<const ulonglong2*>(&Bs[cur][kk][tn + 4]);
#pragma unroll
            for (int i = 0; i < 4; i++) {
                fma2(acc[i][0], ad[i], bv0.x);
                fma2(acc[i][1], ad[i], bv0.y);
                fma2(acc[i][2], ad[i], bv1.x);
                fma2(acc[i][3], ad[i], bv1.y);
            }
        }
        if (more) {
            const int nxt = cur ^ 1;
            As[nxt][ak + 0][am] = ar0.x; As[nxt][ak + 1][am] = ar0.y;
            As[nxt][ak + 2][am] = ar0.z; As[nxt][ak + 3][am] = ar0.w;
            *reinterpret_cast<float4*>(&Bs[nxt][bk][bn]) = br0;
            *reinterpret_cast<float4*>(&Bs[nxt][bk][bn + 4]) = br1;
        }
        __syncthreads();
    }

#pragma unroll
    for (int i = 0; i < 4; i++) {
        float* crow = C + (long)(tm + i) * N;
        float2 v[4];
        v[0] = unpack2(acc[i][0]); v[1] = unpack2(acc[i][1]);
        v[2] = unpack2(acc[i][2]); v[3] = unpack2(acc[i][3]);
#pragma unroll
        for (int j = 0; j < 4; j++) {
            int gn = n0 + tn + 2 * j;
            atomicAdd(crow + gn, v[j].x);
            atomicAdd(crow + gn + 1, v[j].y);
        }
    }
}

// P4: LSTM pointwise + next-step prep (128 CTAs)
__global__ void __launch_bounds__(256) k_lstm(const int* __restrict__ captions,
                                              const float* __restrict__ emb, int t) {
    int idx = blockIdx.x * 256 + threadIdx.x;
    int b = idx >> 9, d = idx & 511;
    float* gg = g_gates + b * 2048;
    float ig = sigf(gg[d]);
    float fg = sigf(gg[512 + d]);
    float gv = tanhf(gg[1024 + d]);
    float og = sigf(gg[1536 + d]);
    float c2 = fg * g_c[idx] + ig * gv;
    float h2 = og * tanhf(c2);
    g_c[idx] = c2;
    g_h[idx] = h2;
    g_H[((long)(t - 1) * BATCH + b) * 512 + d] = h2;
    g_x[b * 1536 + 1024 + d] = h2;
    gg[d]        = g_bias4[d];
    gg[512 + d]  = g_bias4[512 + d];
    gg[1024 + d] = g_bias4[1024 + d];
    gg[1536 + d] = g_bias4[1536 + d];
    if (t < TT - 1) {
        int tok = captions[b * TT + t];
        g_x[b * 1536 + d] = emb[(long)tok * 512 + d];
    }
}

// ---------------- launcher ----------------
extern "C" void kernel_launch(void* const* d_in, const int* in_sizes, int n_in,
                              void* d_out, int out_size) {
    const float* encoder_feats  = (const float*)d_in[0];
    const float* encoder_pooled = (const float*)d_in[1];
    const int*   captions       = (const int*)d_in[2];
    const float* We_att  = (const float*)d_in[3];
    const float* be_att  = (const float*)d_in[4];
    const float* Wd_att  = (const float*)d_in[5];
    const float* bd_att  = (const float*)d_in[6];
    const float* wf_att  = (const float*)d_in[7];
    const float* emb_table = (const float*)d_in[9];
    const float* W_ih = (const float*)d_in[10];
    const float* W_hh = (const float*)d_in[11];
    const float* b_ih = (const float*)d_in[12];
    const float* b_hh = (const float*)d_in[13];
    const float* W_init_h = (const float*)d_in[14];
    const float* b_init_h = (const float*)d_in[15];
    const float* W_init_c = (const float*)d_in[16];
    const float* b_init_c = (const float*)d_in[17];
    const float* W_fc  = (const float*)d_in[18];
    const float* b_fc  = (const float*)d_in[19];
    const float* W_beta = (const float*)d_in[20];
    const float* b_beta = (const float*)d_in[21];
    float* out = (float*)d_out;

    void* p;
    cudaGetSymbolAddress(&p, g_x);     float* x_ptr = (float*)p;
    cudaGetSymbolAddress(&p, g_Wcat);  float* wcat_ptr = (float*)p;
    cudaGetSymbolAddress(&p, g_gates); float* gates_ptr = (float*)p;
    cudaGetSymbolAddress(&p, g_H);     float* H_ptr = (float*)p;
    cudaGetSymbolAddress(&p, g_Aext);  __nv_bfloat16* Aext = (__nv_bfloat16*)p;
    cudaGetSymbolAddress(&p, g_Bext);  __nv_bfloat16* Bext = (__nv_bfloat16*)p;
    cudaGetSymbolAddress(&p, g_Wext);  __nv_bfloat16* Wext = (__nv_bfloat16*)p;

    const int SMEM = 64 * 1024;
    cudaFuncSetAttribute(mma_gemm<0>, cudaFuncAttributeMaxDynamicSharedMemorySize, SMEM);
    cudaFuncSetAttribute(mma_gemm<2>, cudaFuncAttributeMaxDynamicSharedMemorySize, SMEM);

    // lazily-created side stream + events (created once; no device-mem alloc)
    static cudaStream_t s1 = nullptr;
    static cudaEvent_t evFork = nullptr, evC[4], evJoin = nullptr;
    if (!s1) {
        cudaStreamCreateWithFlags(&s1, cudaStreamNonBlocking);
        cudaEventCreateWithFlags(&evFork, cudaEventDisableTiming);
        for (int i = 0; i < 4; i++) cudaEventCreateWithFlags(&evC[i], cudaEventDisableTiming);
        cudaEventCreateWithFlags(&evJoin, cudaEventDisableTiming);
    }

    // fork side stream into the captured graph
    cudaEventRecord(evFork, 0);
    cudaStreamWaitEvent(s1, evFork, 0);

    // ---- stream1: independent prologue (zero t=0 plane, W_fc transpose) ----
    k_zero_t0<<<(BATCH * VV + 255) / 256, 256, 0, s1>>>(out);
    k_tsp_ext<<<dim3(940, 16), dim3(32, 8), 0, s1>>>(W_fc, Bext, VV, NPAD);

    // ---- stream0: critical-path prologue ----
    k_init_hc<<<dim3(4, BATCH), 256>>>(encoder_pooled, W_init_h, b_init_h, W_init_c, b_init_c);
    k_wcat<<<(1536 * 2048 + 255) / 256, 256>>>(W_ih, W_hh, b_ih, b_hh, bd_att, b_beta, wf_att);
    k_tspf<<<dim3(16, 16), dim3(32, 8)>>>(Wd_att, 0);
    k_tspf<<<dim3(16, 16), dim3(32, 8)>>>(W_beta, 512);
    k_tsp_ext<<<dim3(16, 16), dim3(32, 8)>>>(We_att, Wext, 512, 512);
    k_cvt_ext<<<(12544 * 512 + 255) / 256, 256>>>(encoder_feats, Aext, 12544 * 512);
    k_prep0<<<128, 256>>>(captions, emb_table);
    mma_gemm<0><<<dim3(4, 98), 256, SMEM>>>(Aext, Wext, nullptr, be_att, 12544, 512, 0);

    // ---- recurrence: 4 launches per step; vocab-chunk events at steps 8/16/24/29 ----
    int chunkIdx = 0;
    for (int t = 1; t < TT; t++) {
        k_gemv<<<128, 256>>>();
        k_attall<<<64, 256>>>(encoder_feats);
        gemm_gates<<<dim3(16, 1, 8), 256>>>(x_ptr, wcat_ptr, gates_ptr, 2048, 1536, 192);
        k_lstm<<<128, 256>>>(captions, emb_table, t);
        if (t == 8 || t == 16 || t == 24 || t == 29) {
            cudaEventRecord(evC[chunkIdx], 0);
            chunkIdx++;
        }
    }

    // ---- stream1: vocab chunks overlapped with recurrence ----
    const int rowOff[4]  = { 0, 512, 1024, 1536 };
    const int rowCnt[4]  = { 512, 512, 512, 384 };   // last: 320 real + 64 zero pad
    for (int c = 0; c < 4; c++) {
        cudaStreamWaitEvent(s1, evC[c], 0);
        k_cvt_ext<<<(rowCnt[c] * 512 + 255) / 256, 256, 0, s1>>>(
            H_ptr + (long)rowOff[c] * 512, Aext + (long)rowOff[c] * KEXT, rowCnt[c] * 512);
        mma_gemm<2><<<dim3(NPAD / 128, rowCnt[c] / 128), 256, SMEM, s1>>>(
            Aext, Bext, out, b_fc, (TT - 1) * BATCH, VV, rowOff[c]);
    }

    // ---- join ----
    cudaEventRecord(evJoin, s1);
    cudaStreamWaitEvent(0, evJoin, 0);
}

// round 8
// speedup vs baseline: 1.0442x; 1.0442x over previous
#include <cuda_runtime.h>
#include <cuda_bf16.h>
#include <cuda_fp16.h>
#include <math.h>
#include <stdint.h>

// Problem dims
#define BATCH 64
#define PP    196
#define TT    30
#define VV    30000
#define NPAD  30080
#define KEXT  1536      // 3 x 512 (hi*hi + hi*lo + lo*hi)

// ---------------- device scratch ----------------
__device__ float g_h[BATCH * 512];
__device__ float g_c[BATCH * 512];
__device__ float g_hgate[BATCH * 512];
__device__ float g_x[BATCH * 1536];               // [emb | ctx | h]
__device__ float g_gates[BATCH * 2048];
__device__ float g_Wcat[1536 * 2048];
__device__ float g_bias4[2048];
__device__ float g_biasdb[1024];                  // [bd_att | b_beta]
__device__ float g_WdbT[1024 * 512];              // [Wd | W_beta]^T fp32
__device__ float g_H[TT * BATCH * 512];           // 1920 rows (1856 real)

__device__ __half2 g_ep2[12544 * 256];            // enc_proj half2
__device__ __half2 g_dp2[BATCH * 256];            // dec_proj half2
__device__ __half2 g_wf2[256];

__device__ __nv_bfloat16 g_Aext[12544 * KEXT];
__device__ __nv_bfloat16 g_Bext[NPAD * KEXT];
__device__ __nv_bfloat16 g_Wext[512 * KEXT];

__device__ __forceinline__ float sigf(float x) { return 1.f / (1.f + expf(-x)); }
__device__ __forceinline__ uint32_t smem_u32(const void* p) {
    uint32_t a;
    asm("{ .reg .u64 t; cvta.to.shared.u64 t, %1; cvt.u32.u64 %0, t; }" : "=r"(a) : "l"(p));
    return a;
}
__device__ __forceinline__ __half2 tanh2(__half2 v) {
    uint32_t u = *reinterpret_cast<uint32_t*>(&v), r;
    asm("tanh.approx.f16x2 %0, %1;" : "=r"(r) : "r"(u));
    return *reinterpret_cast<__half2*>(&r);
}

// ---------------- mma.sync bf16 GEMM ----------------
#define NSTAGE (KEXT / 64)   // 24

__device__ __forceinline__ void ldm4(uint32_t* r, uint32_t addr) {
    asm volatile("ldmatrix.sync.aligned.m8n8.x4.shared.b16 {%0,%1,%2,%3}, [%4];"
        : "=r"(r[0]), "=r"(r[1]), "=r"(r[2]), "=r"(r[3]) : "r"(addr));
}
__device__ __forceinline__ void mma16816(float* c, const uint32_t* a, uint32_t b0, uint32_t b1) {
    asm volatile("mma.sync.aligned.m16n8k16.row.col.f32.bf16.bf16.f32 "
        "{%0,%1,%2,%3}, {%4,%5,%6,%7}, {%8,%9}, {%0,%1,%2,%3};"
        : "+f"(c[0]), "+f"(c[1]), "+f"(c[2]), "+f"(c[3])
        : "r"(a[0]), "r"(a[1]), "r"(a[2]), "r"(a[3]), "r"(b0), "r"(b1));
}
#define CPA(saddr, gaddr) \
    asm volatile("cp.async.cg.shared.global [%0], [%1], 16;" :: "r"(saddr), "l"(gaddr))
#define CPA_COMMIT() asm volatile("cp.async.commit_group;")
#define CPA_WAIT0()  asm volatile("cp.async.wait_group 0;")

// EPI 0: enc_proj -> g_ep2 half2 (+bias). EPI 2: vocab scatter + bias.
template <int EPI>
__global__ void __launch_bounds__(256) mma_gemm(
    const __nv_bfloat16* __restrict__ Aext, const __nv_bfloat16* __restrict__ Bext,
    float* __restrict__ C, const float* __restrict__ bias,
    int Mreal, int Nreal)
{
    extern __shared__ char sm[];
    const uint32_t sb = smem_u32(sm);
    const int tid = threadIdx.x;
    const int m0 = blockIdx.y * 128;
    const int n0 = blockIdx.x * 128;

    const __nv_bfloat16* Ag = Aext + (long)m0 * KEXT;
    const __nv_bfloat16* Bg = Bext + (long)n0 * KEXT;

    const int wid = tid >> 5, lane = tid & 31;
    const int wm = wid & 3, wn = wid >> 2;
    const int g = lane >> 3, r = lane & 7;
    const int lrow = (g & 1) * 8 + r;
    const uint32_t lkb = (g >> 1) * 16;
    const uint32_t xorp = (uint32_t)(r << 4);

    uint32_t aoff[2], boff[4];
#pragma unroll
    for (int mt = 0; mt < 2; mt++) aoff[mt] = (uint32_t)((wm * 32 + mt * 16 + lrow) * 128);
#pragma unroll
    for (int bt = 0; bt < 4; bt++) boff[bt] = (uint32_t)(16384 + (wn * 64 + bt * 16 + lrow) * 128);

    float acc[2][8][4];
#pragma unroll
    for (int i = 0; i < 2; i++)
#pragma unroll
        for (int j = 0; j < 8; j++)
#pragma unroll
            for (int q = 0; q < 4; q++) acc[i][j][q] = 0.f;

    {
#pragma unroll
        for (int i = 0; i < 4; i++) {
            int idx = i * 256 + tid;
            int row = idx >> 3, c = idx & 7;
            uint32_t so = (uint32_t)(row * 128 + ((c * 16) ^ ((row & 7) << 4)));
            CPA(sb + so, Ag + (long)row * KEXT + c * 8);
            CPA(sb + 16384 + so, Bg + (long)row * KEXT + c * 8);
        }
        CPA_COMMIT();
    }

    for (int s = 0; s < NSTAGE; s++) {
        CPA_WAIT0();
        __syncthreads();
        if (s + 1 < NSTAGE) {
            const uint32_t dstb = sb + ((s + 1) & 1) * 32768;
            const long kb = (long)(s + 1) * 64;
#pragma unroll
            for (int i = 0; i < 4; i++) {
                int idx = i * 256 + tid;
                int row = idx >> 3, c = idx & 7;
                uint32_t so = (uint32_t)(row * 128 + ((c * 16) ^ ((row & 7) << 4)));
                CPA(dstb + so, Ag + (long)row * KEXT + kb + c * 8);
                CPA(dstb + 16384 + so, Bg + (long)row * KEXT + kb + c * 8);
            }
            CPA_COMMIT();
        }

        const uint32_t sbase = sb + (s & 1) * 32768;
#pragma unroll
        for (int kk = 0; kk < 4; kk++) {
            const uint32_t kb = (uint32_t)(kk * 32 + lkb) ^ xorp;
            uint32_t a0[4], a1[4];
            ldm4(a0, sbase + aoff[0] + kb);
            ldm4(a1, sbase + aoff[1] + kb);
#pragma unroll
            for (int bt = 0; bt < 4; bt++) {
                uint32_t bm[4];
                ldm4(bm, sbase + boff[bt] + kb);
                mma16816(acc[0][2 * bt],     a0, bm[0], bm[2]);
                mma16816(acc[1][2 * bt],     a1, bm[0], bm[2]);
                mma16816(acc[0][2 * bt + 1], a0, bm[1], bm[3]);
                mma16816(acc[1][2 * bt + 1], a1, bm[1], bm[3]);
            }
        }
        __syncthreads();
    }

    const int crow0 = lane >> 2;
    const int ccol = (lane & 3) * 2;
#pragma unroll
    for (int mt = 0; mt < 2; mt++) {
#pragma unroll
        for (int h = 0; h < 2; h++) {
            const int m = m0 + wm * 32 + mt * 16 + crow0 + h * 8;
            if (EPI == 0) {
#pragma unroll
                for (int nt = 0; nt < 8; nt++) {
                    const int n = n0 + wn * 64 + nt * 8 + ccol;
                    float vx = acc[mt][nt][h * 2 + 0] + bias[n];
                    float vy = acc[mt][nt][h * 2 + 1] + bias[n + 1];
                    g_ep2[(long)m * 256 + (n >> 1)] = __floats2half2_rn(vx, vy);
                }
            } else {
                if (m < Mreal) {
                    int t = (m >> 6) + 1;
                    int b = m & 63;
                    float* crow = C + (long)b * (TT * VV) + (long)t * VV;
#pragma unroll
                    for (int nt = 0; nt < 8; nt++) {
                        const int n = n0 + wn * 64 + nt * 8 + ccol;
                        if (n < Nreal) {
                            float2 o;
                            o.x = acc[mt][nt][h * 2 + 0] + bias[n];
                            o.y = acc[mt][nt][h * 2 + 1] + bias[n + 1];
                            *reinterpret_cast<float2*>(crow + n) = o;
                        }
                    }
                }
            }
        }
    }
}

// ---------------- conversion kernels ----------------
__global__ void k_cvt_ext(const float* __restrict__ src, __nv_bfloat16* __restrict__ dst, int n) {
    int i = blockIdx.x * 256 + threadIdx.x;
    if (i < n) {
        int row = i >> 9, k = i & 511;
        float x = src[i];
        __nv_bfloat16 h = __float2bfloat16(x);
        __nv_bfloat16 l = __float2bfloat16(x - __bfloat162float(h));
        __nv_bfloat16* d = dst + (long)row * KEXT + k;
        d[0] = h; d[512] = h; d[1024] = l;
    }
}

__global__ void k_tsp_ext(const float* __restrict__ src, __nv_bfloat16* __restrict__ dst,
                          int N, int Npad) {
    __shared__ float t[32][33];
    int n0 = blockIdx.x * 32, k0 = blockIdx.y * 32;
    int tx = threadIdx.x, ty = threadIdx.y;
#pragma unroll
    for (int i = 0; i < 32; i += 8) {
        int k = k0 + ty + i, n = n0 + tx;
        t[ty + i][tx] = (n < N) ? src[(long)k * N + n] : 0.f;
    }
    __syncthreads();
#pragma unroll
    for (int i = 0; i < 32; i += 8) {
        int n = n0 + ty + i, k = k0 + tx;
        if (n < Npad) {
            float x = t[tx][ty + i];
            __nv_bfloat16 h = __float2bfloat16(x);
            __nv_bfloat16 l = __float2bfloat16(x - __bfloat162float(h));
            __nv_bfloat16* d = dst + (long)n * KEXT + k;
            d[0] = h; d[512] = l; d[1024] = h;
        }
    }
}

__global__ void k_tspf(const float* __restrict__ src, int off) {
    __shared__ float t[32][33];
    int n0 = blockIdx.x * 32, k0 = blockIdx.y * 32;
    int tx = threadIdx.x, ty = threadIdx.y;
#pragma unroll
    for (int i = 0; i < 32; i += 8)
        t[ty + i][tx] = src[(long)(k0 + ty + i) * 512 + n0 + tx];
    __syncthreads();
#pragma unroll
    for (int i = 0; i < 32; i += 8)
        g_WdbT[(long)(off + n0 + ty + i) * 512 + k0 + tx] = t[tx][ty + i];
}

// ---------------- prologue kernels ----------------
__global__ void k_zero_t0(float* __restrict__ out) {
    int idx = blockIdx.x * 256 + threadIdx.x;
    if (idx < BATCH * VV) {
        int b = idx / VV, v = idx - b * VV;
        out[(long)b * (TT * VV) + v] = 0.f;
    }
}

__global__ void k_init_hc(const float* __restrict__ pooled,
                          const float* __restrict__ Wh, const float* __restrict__ bh,
                          const float* __restrict__ Wc, const float* __restrict__ bc) {
    int b = blockIdx.y;
    int j = blockIdx.x * 256 + threadIdx.x;
    __shared__ float pr[512];
    pr[threadIdx.x] = pooled[b * 512 + threadIdx.x];
    pr[threadIdx.x + 256] = pooled[b * 512 + threadIdx.x + 256];
    __syncthreads();
    float a0 = 0, a1 = 0, a2 = 0, a3 = 0;
    const float* W = (j < 512) ? (Wh + j) : (Wc + j - 512);
    for (int k = 0; k < 512; k += 4) {
        a0 += pr[k] * W[k * 512];
        a1 += pr[k + 1] * W[(k + 1) * 512];
        a2 += pr[k + 2] * W[(k + 2) * 512];
        a3 += pr[k + 3] * W[(k + 3) * 512];
    }
    float s = (a0 + a1) + (a2 + a3);
    if (j < 512) g_h[b * 512 + j] = tanhf(s + bh[j]);
    else         g_c[b * 512 + (j - 512)] = tanhf(s + bc[j - 512]);
}

__global__ void k_wcat(const float* __restrict__ Wih, const float* __restrict__ Whh,
                       const float* __restrict__ bih, const float* __restrict__ bhh,
                       const float* __restrict__ bd, const float* __restrict__ bb,
                       const float* __restrict__ wf) {
    int idx = blockIdx.x * 256 + threadIdx.x;
    if (idx < 1536 * 2048) {
        int k = idx >> 11, n = idx & 2047;
        g_Wcat[idx] = (k < 1024) ? Wih[idx] : Whh[(k - 1024) * 2048 + n];
    }
    if (idx < 2048) g_bias4[idx] = bih[idx] + bhh[idx];
    if (idx < 1024) g_biasdb[idx] = (idx < 512) ? bd[idx] : bb[idx - 512];
    if (idx < 256)  g_wf2[idx] = __floats2half2_rn(wf[2 * idx], wf[2 * idx + 1]);
}

__global__ void k_prep0(const int* __restrict__ captions, const float* __restrict__ emb) {
    int idx = blockIdx.x * 256 + threadIdx.x;    // 32768
    int b = idx >> 9, d = idx & 511;
    int tok = captions[b * TT];
    g_x[b * 1536 + d] = emb[(long)tok * 512 + d];
    g_x[b * 1536 + 1024 + d] = g_h[idx];
    g_gates[b * 2048 + d]        = g_bias4[d];
    g_gates[b * 2048 + 512 + d]  = g_bias4[512 + d];
    g_gates[b * 2048 + 1024 + d] = g_bias4[1024 + d];
    g_gates[b * 2048 + 1536 + d] = g_bias4[1536 + d];
    g_H[1856 * 512 + idx] = 0.f;   // zero the padded H tail
}

// ---------------- per-step kernels ----------------
// P1: dec_proj + gate, warp-per-j GEMV (128 CTAs); weights read ONCE
__global__ void __launch_bounds__(256) k_gemv() {
    const int wid = threadIdx.x >> 5, lane = threadIdx.x & 31;
    const int j = blockIdx.x * 8 + wid;   // 0..1023
    float wt[16];
    const float* wrow = g_WdbT + (long)j * 512;
#pragma unroll
    for (int i = 0; i < 16; i++) wt[i] = wrow[lane + i * 32];
    const float bias = g_biasdb[j];
#pragma unroll 2
    for (int b = 0; b < 64; b++) {
        const float* hb = g_h + b * 512;
        float acc = 0.f;
#pragma unroll
        for (int i = 0; i < 16; i++) acc += wt[i] * hb[lane + i * 32];
#pragma unroll
        for (int o = 16; o; o >>= 1) acc += __shfl_down_sync(0xffffffffu, acc, o);
        if (lane == 0) {
            float s = acc + bias;
            if (j < 512) reinterpret_cast<__half*>(g_dp2)[b * 512 + j] = __float2half(s);
            else         g_hgate[b * 512 + (j - 512)] = sigf(s);
        }
    }
}

// P2: scores + softmax + gated ctx (64 CTAs, one per batch)
__global__ void __launch_bounds__(256) k_attall(const float* __restrict__ feats) {
    const int b = blockIdx.x;
    const int tid = threadIdx.x;
    const int wid = tid >> 5, lane = tid & 31;
    __shared__ __half2 sdp[256], swf[256];
    __shared__ float sc[256], sred[256];
    sdp[tid] = g_dp2[b * 256 + tid];
    swf[tid] = g_wf2[tid];
    if (tid >= PP) sc[tid] = -1e30f;
    __syncthreads();
    for (int rr = 0; rr < 25; rr++) {
        int p = rr * 8 + wid;
        if (p < PP) {
            const __half2* ep = g_ep2 + (long)(b * PP + p) * 256;
            float accf = 0.f;
#pragma unroll
            for (int u = 0; u < 2; u++) {
                int i0 = u * 128 + lane * 4;
                uint4 ev = *reinterpret_cast<const uint4*>(ep + i0);
                const __half2* e2 = reinterpret_cast<const __half2*>(&ev);
#pragma unroll
                for (int jj = 0; jj < 4; jj += 2) {
                    __half2 t0 = tanh2(__hadd2(e2[jj],     sdp[i0 + jj]));
                    __half2 t1 = tanh2(__hadd2(e2[jj + 1], sdp[i0 + jj + 1]));
                    __half2 a2 = __hfma2(t1, swf[i0 + jj + 1], __hmul2(t0, swf[i0 + jj]));
                    float2 f = __half22float2(a2);
                    accf += f.x + f.y;
                }
            }
#pragma unroll
            for (int o = 16; o; o >>= 1) accf += __shfl_down_sync(0xffffffffu, accf, o);
            if (lane == 0) sc[p] = accf;
        }
    }
    __syncthreads();
    float v = sc[tid];
    sred[tid] = v;
    __syncthreads();
    for (int s = 128; s > 0; s >>= 1) {
        if (tid < s) sred[tid] = fmaxf(sred[tid], sred[tid + s]);
        __syncthreads();
    }
    float mx = sred[0];
    __syncthreads();
    float e = (tid < PP) ? expf(v - mx) : 0.f;
    sred[tid] = e;
    __syncthreads();
    for (int s = 128; s > 0; s >>= 1) {
        if (tid < s) sred[tid] += sred[tid + s];
        __syncthreads();
    }
    float inv = 1.f / sred[0];
    __syncthreads();
    sc[tid] = e * inv;
    __syncthreads();
    const float* fb = feats + (long)b * PP * 512;
#pragma unroll
    for (int half = 0; half < 2; half++) {
        int d = half * 256 + tid;
        float acc = 0.f;
        const float* fp = fb + d;
#pragma unroll 4
        for (int p = 0; p < PP; p++) acc += sc[p] * fp[p * 512];
        g_x[b * 1536 + 512 + d] = acc * g_hgate[b * 512 + d];
    }
}

// ---------------- packed f32x2 helpers + gates GEMM ----------------
__device__ __forceinline__ unsigned long long pack2(float x) {
    unsigned long long r;
    asm("mov.b64 %0, {%1, %1};" : "=l"(r) : "f"(x));
    return r;
}
__device__ __forceinline__ void fma2(unsigned long long& d, unsigned long long a, unsigned long long b) {
    asm("fma.rn.f32x2 %0, %1, %2, %0;" : "+l"(d) : "l"(a), "l"(b));
}
__device__ __forceinline__ float2 unpack2(unsigned long long v) {
    float2 r;
    asm("mov.b64 {%0, %1}, %2;" : "=f"(r.x), "=f"(r.y) : "l"(v));
    return r;
}

__global__ void __launch_bounds__(256) gemm_gates(
    const float* __restrict__ A, const float* __restrict__ B,
    float* __restrict__ C, int N, int K, int kLen)
{
    __shared__ float As[2][16][64];
    __shared__ float Bs[2][16][128];

    const int tid = threadIdx.x;
    const int n0 = blockIdx.x * 128;
    const int kStart = blockIdx.z * kLen;
    const int tn = (tid & 15) * 8;
    const int tm = (tid >> 4) * 4;
    const int am = tid >> 2, ak = (tid & 3) * 4;
    const int bk = tid >> 4, bn = (tid & 15) * 8;

    const float* Aptr = A + (long)am * K + kStart + ak;
    const float* Bptr = B + (long)(kStart + bk) * N + n0 + bn;

    unsigned long long acc[4][4];
#pragma unroll
    for (int i = 0; i < 4; i++) acc[i][0] = acc[i][1] = acc[i][2] = acc[i][3] = 0ull;

    const int nb = kLen / 16;
    float4 ar0, br0, br1;
    ar0 = *reinterpret_cast<const float4*>(Aptr);
    br0 = *reinterpret_cast<const float4*>(Bptr);
    br1 = *reinterpret_cast<const float4*>(Bptr + 4);
    As[0][ak + 0][am] = ar0.x; As[0][ak + 1][am] = ar0.y;
    As[0][ak + 2][am] = ar0.z; As[0][ak + 3][am] = ar0.w;
    *reinterpret_cast<float4*>(&Bs[0][bk][bn]) = br0;
    *reinterpret_cast<float4*>(&Bs[0][bk][bn + 4]) = br1;
    __syncthreads();

    for (int ib = 0; ib < nb; ib++) {
        const int cur = ib & 1;
        const bool more = (ib + 1) < nb;
        if (more) {
            ar0 = *reinterpret_cast<const float4*>(Aptr + (ib + 1) * 16);
            const float* bp = Bptr + (long)((ib + 1) * 16) * N;
            br0 = *reinterpret_cast<const float4*>(bp);
            br1 = *reinterpret_cast<const float4*>(bp + 4);
        }
#pragma unroll
        for (int kk = 0; kk < 16; kk++) {
            unsigned long long ad[4];
            float4 af = *reinterpret_cast<const float4*>(&As[cur][kk][tm]);
            ad[0] = pack2(af.x); ad[1] = pack2(af.y); ad[2] = pack2(af.z); ad[3] = pack2(af.w);
            ulonglong2 bv0 = *reinterpret_cast<const ulonglong2*>(&Bs[cur][kk][tn]);
            ulonglong2 bv1 = *reinterpret_cast<const ulonglong2*>(&Bs[cur][kk][tn + 4]);
#pragma unroll
            for (int i = 0; i < 4; i++) {
                fma2(acc[i][0], ad[i], bv0.x);
                fma2(acc[i][1], ad[i], bv0.y);
                fma2(acc[i][2], ad[i], bv1.x);
                fma2(acc[i][3], ad[i], bv1.y);
            }
        }
        if (more) {
            const int nxt = cur ^ 1;
            As[nxt][ak + 0][am] = ar0.x; As[nxt][ak + 1][am] = ar0.y;
            As[nxt][ak + 2][am] = ar0.z; As[nxt][ak + 3][am] = ar0.w;
            *reinterpret_cast<float4*>(&Bs[nxt][bk][bn]) = br0;
            *reinterpret_cast<float4*>(&Bs[nxt][bk][bn + 4]) = br1;
        }
        __syncthreads();
    }

#pragma unroll
    for (int i = 0; i < 4; i++) {
        float* crow = C + (long)(tm + i) * N;
        float2 v[4];
        v[0] = unpack2(acc[i][0]); v[1] = unpack2(acc[i][1]);
        v[2] = unpack2(acc[i][2]); v[3] = unpack2(acc[i][3]);
#pragma unroll
        for (int j = 0; j < 4; j++) {
            int gn = n0 + tn + 2 * j;
            atomicAdd(crow + gn, v[j].x);
            atomicAdd(crow + gn + 1, v[j].y);
        }
    }
}

// P4: LSTM pointwise + next-step prep (128 CTAs)
__global__ void __launch_bounds__(256) k_lstm(const int* __restrict__ captions,
                                              const float* __restrict__ emb, int t) {
    int idx = blockIdx.x * 256 + threadIdx.x;
    int b = idx >> 9, d = idx & 511;
    float* gg = g_gates + b * 2048;
    float ig = sigf(gg[d]);
    float fg = sigf(gg[512 + d]);
    float gv = tanhf(gg[1024 + d]);
    float og = sigf(gg[1536 + d]);
    float c2 = fg * g_c[idx] + ig * gv;
    float h2 = og * tanhf(c2);
    g_c[idx] = c2;
    g_h[idx] = h2;
    g_H[((long)(t - 1) * BATCH + b) * 512 + d] = h2;
    g_x[b * 1536 + 1024 + d] = h2;
    gg[d]        = g_bias4[d];
    gg[512 + d]  = g_bias4[512 + d];
    gg[1024 + d] = g_bias4[1024 + d];
    gg[1536 + d] = g_bias4[1536 + d];
    if (t < TT - 1) {
        int tok = captions[b * TT + t];
        g_x[b * 1536 + d] = emb[(long)tok * 512 + d];
    }
}

// ---------------- launcher ----------------
extern "C" void kernel_launch(void* const* d_in, const int* in_sizes, int n_in,
                              void* d_out, int out_size) {
    const float* encoder_feats  = (const float*)d_in[0];
    const float* encoder_pooled = (const float*)d_in[1];
    const int*   captions       = (const int*)d_in[2];
    const float* We_att  = (const float*)d_in[3];
    const float* be_att  = (const float*)d_in[4];
    const float* Wd_att  = (const float*)d_in[5];
    const float* bd_att  = (const float*)d_in[6];
    const float* wf_att  = (const float*)d_in[7];
    const float* emb_table = (const float*)d_in[9];
    const float* W_ih = (const float*)d_in[10];
    const float* W_hh = (const float*)d_in[11];
    const float* b_ih = (const float*)d_in[12];
    const float* b_hh = (const float*)d_in[13];
    const float* W_init_h = (const float*)d_in[14];
    const float* b_init_h = (const float*)d_in[15];
    const float* W_init_c = (const float*)d_in[16];
    const float* b_init_c = (const float*)d_in[17];
    const float* W_fc  = (const float*)d_in[18];
    const float* b_fc  = (const float*)d_in[19];
    const float* W_beta = (const float*)d_in[20];
    const float* b_beta = (const float*)d_in[21];
    float* out = (float*)d_out;

    void* p;
    cudaGetSymbolAddress(&p, g_x);     float* x_ptr = (float*)p;
    cudaGetSymbolAddress(&p, g_Wcat);  float* wcat_ptr = (float*)p;
    cudaGetSymbolAddress(&p, g_gates); float* gates_ptr = (float*)p;
    cudaGetSymbolAddress(&p, g_H);     float* H_ptr = (float*)p;
    cudaGetSymbolAddress(&p, g_Aext);  __nv_bfloat16* Aext = (__nv_bfloat16*)p;
    cudaGetSymbolAddress(&p, g_Bext);  __nv_bfloat16* Bext = (__nv_bfloat16*)p;
    cudaGetSymbolAddress(&p, g_Wext);  __nv_bfloat16* Wext = (__nv_bfloat16*)p;

    const int SMEM = 64 * 1024;
    cudaFuncSetAttribute(mma_gemm<0>, cudaFuncAttributeMaxDynamicSharedMemorySize, SMEM);
    cudaFuncSetAttribute(mma_gemm<2>, cudaFuncAttributeMaxDynamicSharedMemorySize, SMEM);

    // ---- prologue (single stream, R4 structure) ----
    k_zero_t0<<<(BATCH * VV + 255) / 256, 256>>>(out);
    k_init_hc<<<dim3(4, BATCH), 256>>>(encoder_pooled, W_init_h, b_init_h, W_init_c, b_init_c);
    k_wcat<<<(1536 * 2048 + 255) / 256, 256>>>(W_ih, W_hh, b_ih, b_hh, bd_att, b_beta, wf_att);
    k_tsp_ext<<<dim3(940, 16), dim3(32, 8)>>>(W_fc, Bext, VV, NPAD);
    k_tsp_ext<<<dim3(16, 16), dim3(32, 8)>>>(We_att, Wext, 512, 512);
    k_tspf<<<dim3(16, 16), dim3(32, 8)>>>(Wd_att, 0);
    k_tspf<<<dim3(16, 16), dim3(32, 8)>>>(W_beta, 512);
    k_cvt_ext<<<(12544 * 512 + 255) / 256, 256>>>(encoder_feats, Aext, 12544 * 512);
    k_prep0<<<128, 256>>>(captions, emb_table);
    mma_gemm<0><<<dim3(4, 98), 256, SMEM>>>(Aext, Wext, nullptr, be_att, 12544, 512);

    // ---- recurrence: 4 launches per step ----
    for (int t = 1; t < TT; t++) {
        k_gemv<<<128, 256>>>();
        k_attall<<<64, 256>>>(encoder_feats);
        gemm_gates<<<dim3(16, 1, 8), 256>>>(x_ptr, wcat_ptr, gates_ptr, 2048, 1536, 192);
        k_lstm<<<128, 256>>>(captions, emb_table, t);
    }

    // ---- vocab projection (end, single stream) ----
    k_cvt_ext<<<(1920 * 512 + 255) / 256, 256>>>(H_ptr, Aext, 1920 * 512);
    mma_gemm<2><<<dim3(NPAD / 128, 15), 256, SMEM>>>(Aext, Bext, out, b_fc,
                                                     (TT - 1) * BATCH, VV);
}

// round 9
// speedup vs baseline: 1.5497x; 1.4840x over previous
#include <cuda_runtime.h>
#include <cuda_bf16.h>
#include <math.h>
#include <stdint.h>

// Problem dims
#define BATCH 64
#define PP    196
#define TT    30
#define VV    30000
#define NPAD  30080
#define KEXT  1536      // 3 x 512 (hi*hi + hi*lo + lo*hi)

// ---------------- device scratch ----------------
__device__ float g_enc_proj[BATCH * PP * 512];
__device__ float g_h[BATCH * 512];
__device__ float g_c[BATCH * 512];
__device__ float g_hgate[BATCH * 1024];
__device__ float g_scores[BATCH * PP];
__device__ float g_x[BATCH * 1536];
__device__ float g_gates[BATCH * 2048];
__device__ float g_Wcat[1536 * 2048];
__device__ float g_bias4[2048];
__device__ float g_H[TT * BATCH * 512];

__device__ __nv_bfloat16 g_Aext[12544 * KEXT];   // feats ext; reused for H ext
__device__ __nv_bfloat16 g_Bext[NPAD * KEXT];    // W_fc^T ext
__device__ __nv_bfloat16 g_Wext[512 * KEXT];     // We_att^T ext

__device__ __forceinline__ float sigf(float x) { return 1.f / (1.f + expf(-x)); }
__device__ __forceinline__ float tanh_a(float x) {
    float y; asm("tanh.approx.f32 %0, %1;" : "=f"(y) : "f"(x)); return y;
}
__device__ __forceinline__ uint32_t smem_u32(const void* p) {
    uint32_t a;
    asm("{ .reg .u64 t; cvta.to.shared.u64 t, %1; cvt.u32.u64 %0, t; }" : "=r"(a) : "l"(p));
    return a;
}

// ---------------- mma.sync bf16 GEMM: C[M x N] = Aext[M x 1536] * Bext[N x 1536]^T ----------------
// CTA tile 128x128, 8 warps (4x2), warp tile 32x64. K-stage 64, double-buffered cp.async.
// EPI 0: C row-major [M x Nld] + bias. EPI 2: vocab scatter + bias, bounds Mreal/Nreal.

#define NSTAGE (KEXT / 64)   // 24

__device__ __forceinline__ void ldm4(uint32_t* r, uint32_t addr) {
    asm volatile("ldmatrix.sync.aligned.m8n8.x4.shared.b16 {%0,%1,%2,%3}, [%4];"
        : "=r"(r[0]), "=r"(r[1]), "=r"(r[2]), "=r"(r[3]) : "r"(addr));
}
__device__ __forceinline__ void mma16816(float* c, const uint32_t* a, uint32_t b0, uint32_t b1) {
    asm volatile("mma.sync.aligned.m16n8k16.row.col.f32.bf16.bf16.f32 "
        "{%0,%1,%2,%3}, {%4,%5,%6,%7}, {%8,%9}, {%0,%1,%2,%3};"
        : "+f"(c[0]), "+f"(c[1]), "+f"(c[2]), "+f"(c[3])
        : "r"(a[0]), "r"(a[1]), "r"(a[2]), "r"(a[3]), "r"(b0), "r"(b1));
}
#define CPA(saddr, gaddr) \
    asm volatile("cp.async.cg.shared.global [%0], [%1], 16;" :: "r"(saddr), "l"(gaddr))
#define CPA_COMMIT() asm volatile("cp.async.commit_group;")
#define CPA_WAIT0()  asm volatile("cp.async.wait_group 0;")

template <int EPI>
__global__ void __launch_bounds__(256) mma_gemm(
    const __nv_bfloat16* __restrict__ Aext, const __nv_bfloat16* __restrict__ Bext,
    float* __restrict__ C, const float* __restrict__ bias,
    int Nld, int Mreal, int Nreal)
{
    extern __shared__ char sm[];
    const uint32_t sb = smem_u32(sm);
    const int tid = threadIdx.x;
    const int m0 = blockIdx.y * 128;
    const int n0 = blockIdx.x * 128;

    const int lrowA = tid >> 1;
    (void)lrowA;

    const __nv_bfloat16* Ag = Aext + (long)m0 * KEXT;
    const __nv_bfloat16* Bg = Bext + (long)n0 * KEXT;

    const int wid = tid >> 5, lane = tid & 31;
    const int wm = wid & 3, wn = wid >> 2;
    const int g = lane >> 3, r = lane & 7;
    const int lrow = (g & 1) * 8 + r;
    const uint32_t lkb = (g >> 1) * 16;
    const uint32_t xorp = (uint32_t)(r << 4);

    uint32_t aoff[2], boff[4];
#pragma unroll
    for (int mt = 0; mt < 2; mt++) aoff[mt] = (uint32_t)((wm * 32 + mt * 16 + lrow) * 128);
#pragma unroll
    for (int bt = 0; bt < 4; bt++) boff[bt] = (uint32_t)(16384 + (wn * 64 + bt * 16 + lrow) * 128);

    float acc[2][8][4];
#pragma unroll
    for (int i = 0; i < 2; i++)
#pragma unroll
        for (int j = 0; j < 8; j++)
#pragma unroll
            for (int q = 0; q < 4; q++) acc[i][j][q] = 0.f;

    {
#pragma unroll
        for (int i = 0; i < 4; i++) {
            int idx = i * 256 + tid;
            int row = idx >> 3, c = idx & 7;
            uint32_t so = (uint32_t)(row * 128 + ((c * 16) ^ ((row & 7) << 4)));
            CPA(sb + so, Ag + (long)row * KEXT + c * 8);
            CPA(sb + 16384 + so, Bg + (long)row * KEXT + c * 8);
        }
        CPA_COMMIT();
    }

    for (int s = 0; s < NSTAGE; s++) {
        CPA_WAIT0();
        __syncthreads();
        if (s + 1 < NSTAGE) {
            const uint32_t dstb = sb + ((s + 1) & 1) * 32768;
            const long kb = (long)(s + 1) * 64;
#pragma unroll
            for (int i = 0; i < 4; i++) {
                int idx = i * 256 + tid;
                int row = idx >> 3, c = idx & 7;
                uint32_t so = (uint32_t)(row * 128 + ((c * 16) ^ ((row & 7) << 4)));
                CPA(dstb + so, Ag + (long)row * KEXT + kb + c * 8);
                CPA(dstb + 16384 + so, Bg + (long)row * KEXT + kb + c * 8);
            }
            CPA_COMMIT();
        }

        const uint32_t sbase = sb + (s & 1) * 32768;
#pragma unroll
        for (int kk = 0; kk < 4; kk++) {
            const uint32_t kb = (uint32_t)(kk * 32 + lkb) ^ xorp;
            uint32_t a0[4], a1[4];
            ldm4(a0, sbase + aoff[0] + kb);
            ldm4(a1, sbase + aoff[1] + kb);
#pragma unroll
            for (int bt = 0; bt < 4; bt++) {
                uint32_t bm[4];
                ldm4(bm, sbase + boff[bt] + kb);
                mma16816(acc[0][2 * bt],     a0, bm[0], bm[2]);
                mma16816(acc[1][2 * bt],     a1, bm[0], bm[2]);
                mma16816(acc[0][2 * bt + 1], a0, bm[1], bm[3]);
                mma16816(acc[1][2 * bt + 1], a1, bm[1], bm[3]);
            }
        }
        __syncthreads();
    }

    // epilogue
    const int crow0 = lane >> 2;
    const int ccol = (lane & 3) * 2;
#pragma unroll
    for (int mt = 0; mt < 2; mt++) {
#pragma unroll
        for (int h = 0; h < 2; h++) {
            const int m = m0 + wm * 32 + mt * 16 + crow0 + h * 8;
            float* crow;
            bool mok;
            if (EPI == 0) {
                crow = C + (long)m * Nld;
                mok = true;
            } else {
                int t = (m >> 6) + 1;
                int b = m & 63;
                crow = C + (long)b * (TT * VV) + (long)t * VV;
                mok = (m < Mreal);
            }
            if (mok) {
#pragma unroll
                for (int nt = 0; nt < 8; nt++) {
                    const int n = n0 + wn * 64 + nt * 8 + ccol;
                    if (EPI == 0 || n < Nreal) {
                        float2 o;
                        o.x = acc[mt][nt][h * 2 + 0] + bias[n];
                        o.y = acc[mt][nt][h * 2 + 1] + bias[n + 1];
                        *reinterpret_cast<float2*>(crow + n) = o;
                    }
                }
            }
        }
    }
}

// ---------------- conversion kernels ----------------
__global__ void k_cvt_ext(const float* __restrict__ src, __nv_bfloat16* __restrict__ dst, int n) {
    int i = blockIdx.x * 256 + threadIdx.x;
    if (i < n) {
        int row = i >> 9, k = i & 511;
        float x = src[i];
        __nv_bfloat16 h = __float2bfloat16(x);
        __nv_bfloat16 l = __float2bfloat16(x - __bfloat162float(h));
        __nv_bfloat16* d = dst + (long)row * KEXT + k;
        d[0] = h; d[512] = h; d[1024] = l;
    }
}

__global__ void k_tsp_ext(const float* __restrict__ src, __nv_bfloat16* __restrict__ dst,
                          int N, int Npad) {
    __shared__ float t[32][33];
    int n0 = blockIdx.x * 32, k0 = blockIdx.y * 32;
    int tx = threadIdx.x, ty = threadIdx.y;
#pragma unroll
    for (int i = 0; i < 32; i += 8) {
        int k = k0 + ty + i, n = n0 + tx;
        t[ty + i][tx] = (n < N) ? src[(long)k * N + n] : 0.f;
    }
    __syncthreads();
#pragma unroll
    for (int i = 0; i < 32; i += 8) {
        int n = n0 + ty + i, k = k0 + tx;
        if (n < Npad) {
            float x = t[tx][ty + i];
            __nv_bfloat16 h = __float2bfloat16(x);
            __nv_bfloat16 l = __float2bfloat16(x - __bfloat162float(h));
            __nv_bfloat16* d = dst + (long)n * KEXT + k;
            d[0] = h; d[512] = l; d[1024] = h;
        }
    }
}

// ---------------- packed f32x2 SIMT GEMM (gates) ----------------
__device__ __forceinline__ unsigned long long pack2(float x) {
    unsigned long long r;
    asm("mov.b64 %0, {%1, %1};" : "=l"(r) : "f"(x));
    return r;
}
__device__ __forceinline__ void fma2(unsigned long long& d, unsigned long long a, unsigned long long b) {
    asm("fma.rn.f32x2 %0, %1, %2, %0;" : "+l"(d) : "l"(a), "l"(b));
}
__device__ __forceinline__ float2 unpack2(unsigned long long v) {
    float2 r;
    asm("mov.b64 {%0, %1}, %2;" : "=f"(r.x), "=f"(r.y) : "l"(v));
    return r;
}

__global__ void __launch_bounds__(256) gemm_gates(
    const float* __restrict__ A, const float* __restrict__ B,
    float* __restrict__ C, int N, int K, int kLen)
{
    __shared__ float As[2][16][64];
    __shared__ float Bs[2][16][128];

    const int tid = threadIdx.x;
    const int n0 = blockIdx.x * 128;
    const int kStart = blockIdx.z * kLen;
    const int tn = (tid & 15) * 8;
    const int tm = (tid >> 4) * 4;
    const int am = tid >> 2, ak = (tid & 3) * 4;
    const int bk = tid >> 4, bn = (tid & 15) * 8;

    const float* Aptr = A + (long)am * K + kStart + ak;
    const float* Bptr = B + (long)(kStart + bk) * N + n0 + bn;

    unsigned long long acc[4][4];
#pragma unroll
    for (int i = 0; i < 4; i++) acc[i][0] = acc[i][1] = acc[i][2] = acc[i][3] = 0ull;

    const int nb = kLen / 16;
    float4 ar0, br0, br1;
    ar0 = *reinterpret_cast<const float4*>(Aptr);
    br0 = *reinterpret_cast<const float4*>(Bptr);
    br1 = *reinterpret_cast<const float4*>(Bptr + 4);
    As[0][ak + 0][am] = ar0.x; As[0][ak + 1][am] = ar0.y;
    As[0][ak + 2][am] = ar0.z; As[0][ak + 3][am] = ar0.w;
    *reinterpret_cast<float4*>(&Bs[0][bk][bn]) = br0;
    *reinterpret_cast<float4*>(&Bs[0][bk][bn + 4]) = br1;
    __syncthreads();

    for (int ib = 0; ib < nb; ib++) {
        const int cur = ib & 1;
        const bool more = (ib + 1) < nb;
        if (more) {
            ar0 = *reinterpret_cast<const float4*>(Aptr + (ib + 1) * 16);
            const float* bp = Bptr + (long)((ib + 1) * 16) * N;
            br0 = *reinterpret_cast<const float4*>(bp);
            br1 = *reinterpret_cast<const float4*>(bp + 4);
        }
#pragma unroll
        for (int kk = 0; kk < 16; kk++) {
            unsigned long long ad[4];
            float4 af = *reinterpret_cast<const float4*>(&As[cur][kk][tm]);
            ad[0] = pack2(af.x); ad[1] = pack2(af.y); ad[2] = pack2(af.z); ad[3] = pack2(af.w);
            ulonglong2 bv0 = *reinterpret_cast<const ulonglong2*>(&Bs[cur][kk][tn]);
            ulonglong2 bv1 = *reinterpret_cast<const ulonglong2*>(&Bs[cur][kk][tn + 4]);
#pragma unroll
            for (int i = 0; i < 4; i++) {
                fma2(acc[i][0], ad[i], bv0.x);
                fma2(acc[i][1], ad[i], bv0.y);
                fma2(acc[i][2], ad[i], bv1.x);
                fma2(acc[i][3], ad[i], bv1.y);
            }
        }
        if (more) {
            const int nxt = cur ^ 1;
            As[nxt][ak + 0][am] = ar0.x; As[nxt][ak + 1][am] = ar0.y;
            As[nxt][ak + 2][am] = ar0.z; As[nxt][ak + 3][am] = ar0.w;
            *reinterpret_cast<float4*>(&Bs[nxt][bk][bn]) = br0;
            *reinterpret_cast<float4*>(&Bs[nxt][bk][bn + 4]) = br1;
        }
        __syncthreads();
    }

#pragma unroll
    for (int i = 0; i < 4; i++) {
        float* crow = C + (long)(tm + i) * N;
        float2 v[4];
        v[0] = unpack2(acc[i][0]); v[1] = unpack2(acc[i][1]);
        v[2] = unpack2(acc[i][2]); v[3] = unpack2(acc[i][3]);
#pragma unroll
        for (int j = 0; j < 4; j++) {
            int gn = n0 + tn + 2 * j;
            atomicAdd(crow + gn, v[j].x);
            atomicAdd(crow + gn + 1, v[j].y);
        }
    }
}

// ---------------- small kernels ----------------
__global__ void k_zero_t0(float* __restrict__ out) {
    int idx = blockIdx.x * 256 + threadIdx.x;
    if (idx < BATCH * VV) {
        int b = idx / VV, v = idx - b * VV;
        out[(long)b * (TT * VV) + v] = 0.f;
    }
}

__global__ void k_init_hc(const float* __restrict__ pooled,
                          const float* __restrict__ Wh, const float* __restrict__ bh,
                          const float* __restrict__ Wc, const float* __restrict__ bc) {
    int b = blockIdx.y;
    int j = blockIdx.x * 256 + threadIdx.x;
    __shared__ float pr[512];
    pr[threadIdx.x] = pooled[b * 512 + threadIdx.x];
    pr[threadIdx.x + 256] = pooled[b * 512 + threadIdx.x + 256];
    __syncthreads();
    float a0 = 0, a1 = 0, a2 = 0, a3 = 0;
    const float* W = (j < 512) ? (Wh + j) : (Wc + j - 512);
    for (int k = 0; k < 512; k += 4) {
        a0 += pr[k] * W[k * 512];
        a1 += pr[k + 1] * W[(k + 1) * 512];
        a2 += pr[k + 2] * W[(k + 2) * 512];
        a3 += pr[k + 3] * W[(k + 3) * 512];
    }
    float s = (a0 + a1) + (a2 + a3);
    if (j < 512) g_h[b * 512 + j] = tanhf(s + bh[j]);
    else         g_c[b * 512 + (j - 512)] = tanhf(s + bc[j - 512]);
}

__global__ void k_wcat(const float* __restrict__ Wih, const float* __restrict__ Whh,
                       const float* __restrict__ bih, const float* __restrict__ bhh) {
    int idx = blockIdx.x * 256 + threadIdx.x;
    if (idx < 1536 * 2048) {
        int k = idx >> 11, n = idx & 2047;
        g_Wcat[idx] = (k < 1024) ? Wih[idx] : Whh[(k - 1024) * 2048 + n];
    }
    if (idx < 2048) g_bias4[idx] = bih[idx] + bhh[idx];
}

__global__ void k_step1(const int* __restrict__ captions, const float* __restrict__ emb,
                        const float* __restrict__ Wd, const float* __restrict__ bd,
                        const float* __restrict__ Wb, const float* __restrict__ bb, int tm1) {
    int blk = blockIdx.x;
    if (blk < 256) {
        int b = blk >> 2;
        int j = (blk & 3) * 256 + threadIdx.x;
        __shared__ float hr[512];
        hr[threadIdx.x] = g_h[b * 512 + threadIdx.x];
        hr[threadIdx.x + 256] = g_h[b * 512 + threadIdx.x + 256];
        __syncthreads();
        float a0 = 0, a1 = 0, a2 = 0, a3 = 0;
        const float* W = (j < 512) ? (Wd + j) : (Wb + j - 512);
        for (int k = 0; k < 512; k += 4) {
            a0 += hr[k] * W[k * 512];
            a1 += hr[k + 1] * W[(k + 1) * 512];
            a2 += hr[k + 2] * W[(k + 2) * 512];
            a3 += hr[k + 3] * W[(k + 3) * 512];
        }
        float s = (a0 + a1) + (a2 + a3);
        if (j < 512) g_hgate[b * 1024 + j] = s + bd[j];
        else         g_hgate[b * 1024 + j] = sigf(s + bb[j - 512]);
    } else {
        int idx = (blk - 256) * 256 + threadIdx.x;
        if (idx < 32768) {
            int b = idx >> 9, k = idx & 511;
            int tok = captions[b * TT + tm1];
            g_x[b * 1536 + k] = emb[(long)tok * 512 + k];
        } else if (idx < 65536) {
            int r = idx - 32768;
            int b = r >> 9, k = r & 511;
            g_x[b * 1536 + 1024 + k] = g_h[r];
        } else {
            int r = idx - 65536;
            g_gates[r] = g_bias4[r & 2047];
        }
    }
}

__global__ void k_att(const float* __restrict__ wf, const float* __restrict__ bf) {
    int b = blockIdx.x / 25;
    int pc = blockIdx.x % 25;
    __shared__ float dp[512], wfs[512];
    dp[threadIdx.x] = g_hgate[b * 1024 + threadIdx.x];
    dp[threadIdx.x + 256] = g_hgate[b * 1024 + threadIdx.x + 256];
    wfs[threadIdx.x] = wf[threadIdx.x];
    wfs[threadIdx.x + 256] = wf[threadIdx.x + 256];
    __syncthreads();
    int p = pc * 8 + (threadIdx.x >> 5);
    int lane = threadIdx.x & 31;
    if (p < PP) {
        const float* ep = g_enc_proj + ((long)(b * PP + p)) * 512;
        float acc = 0.f;
#pragma unroll
        for (int i = 0; i < 16; i++) {
            int a = i * 32 + lane;
            acc += tanh_a(ep[a] + dp[a]) * wfs[a];
        }
#pragma unroll
        for (int off = 16; off; off >>= 1) acc += __shfl_down_sync(0xffffffffu, acc, off);
        if (lane == 0) g_scores[b * PP + p] = acc + bf[0];
    }
}

__global__ void k_softmax_ctx(const float* __restrict__ feats) {
    int b = blockIdx.x;
    int tid = threadIdx.x;
    __shared__ float sc[256];
    __shared__ float red[256];
    float v = (tid < PP) ? g_scores[b * PP + tid] : -1e30f;
    red[tid] = v;
    __syncthreads();
    for (int s = 128; s > 0; s >>= 1) {
        if (tid < s) red[tid] = fmaxf(red[tid], red[tid + s]);
        __syncthreads();
    }
    float mx = red[0];
    __syncthreads();
    float e = (tid < PP) ? expf(v - mx) : 0.f;
    red[tid] = e;
    __syncthreads();
    for (int s = 128; s > 0; s >>= 1) {
        if (tid < s) red[tid] += red[tid + s];
        __syncthreads();
    }
    sc[tid] = e / red[0];
    __syncthreads();

    int d = blockIdx.y * 256 + tid;
    const float* fp = feats + (long)b * PP * 512 + d;
    float acc = 0.f;
#pragma unroll 4
    for (int p = 0; p < PP; p++) acc += sc[p] * fp[p * 512];
    g_x[b * 1536 + 512 + d] = acc * g_hgate[b * 1024 + 512 + d];
}

__global__ void k_lstm(int tm1) {
    int idx = blockIdx.x * 256 + threadIdx.x;
    int b = idx >> 9, d = idx & 511;
    const float* gg = g_gates + b * 2048;
    float ig = sigf(gg[d]);
    float fg = sigf(gg[512 + d]);
    float gv = tanhf(gg[1024 + d]);
    float og = sigf(gg[1536 + d]);
    float c2 = fg * g_c[idx] + ig * gv;
    float h2 = og * tanhf(c2);
    g_c[idx] = c2;
    g_h[idx] = h2;
    g_H[((long)tm1 * BATCH + b) * 512 + d] = h2;
}

// ---------------- launcher ----------------
extern "C" void kernel_launch(void* const* d_in, const int* in_sizes, int n_in,
                              void* d_out, int out_size) {
    const float* encoder_feats  = (const float*)d_in[0];
    const float* encoder_pooled = (const float*)d_in[1];
    const int*   captions       = (const int*)d_in[2];
    const float* We_att  = (const float*)d_in[3];
    const float* be_att  = (const float*)d_in[4];
    const float* Wd_att  = (const float*)d_in[5];
    const float* bd_att  = (const float*)d_in[6];
    const float* wf_att  = (const float*)d_in[7];
    const float* bf_att  = (const float*)d_in[8];
    const float* emb_table = (const float*)d_in[9];
    const float* W_ih = (const float*)d_in[10];
    const float* W_hh = (const float*)d_in[11];
    const float* b_ih = (const float*)d_in[12];
    const float* b_hh = (const float*)d_in[13];
    const float* W_init_h = (const float*)d_in[14];
    const float* b_init_h = (const float*)d_in[15];
    const float* W_init_c = (const float*)d_in[16];
    const float* b_init_c = (const float*)d_in[17];
    const float* W_fc  = (const float*)d_in[18];
    const float* b_fc  = (const float*)d_in[19];
    const float* W_beta = (const float*)d_in[20];
    const float* b_beta = (const float*)d_in[21];
    float* out = (float*)d_out;

    void* p;
    cudaGetSymbolAddress(&p, g_enc_proj); float* enc_proj_ptr = (float*)p;
    cudaGetSymbolAddress(&p, g_x);        float* x_ptr = (float*)p;
    cudaGetSymbolAddress(&p, g_Wcat);     float* wcat_ptr = (float*)p;
    cudaGetSymbolAddress(&p, g_gates);    float* gates_ptr = (float*)p;
    cudaGetSymbolAddress(&p, g_H);        float* H_ptr = (float*)p;
    cudaGetSymbolAddress(&p, g_Aext);     __nv_bfloat16* Aext = (__nv_bfloat16*)p;
    cudaGetSymbolAddress(&p, g_Bext);     __nv_bfloat16* Bext = (__nv_bfloat16*)p;
    cudaGetSymbolAddress(&p, g_Wext);     __nv_bfloat16* Wext = (__nv_bfloat16*)p;

    const int SMEM = 64 * 1024;
    cudaFuncSetAttribute(mma_gemm<0>, cudaFuncAttributeMaxDynamicSharedMemorySize, SMEM);
    cudaFuncSetAttribute(mma_gemm<2>, cudaFuncAttributeMaxDynamicSharedMemorySize, SMEM);

    // prologue
    k_zero_t0<<<(BATCH * VV + 255) / 256, 256>>>(out);
    k_init_hc<<<dim3(4, BATCH), 256>>>(encoder_pooled, W_init_h, b_init_h, W_init_c, b_init_c);
    k_wcat<<<(1536 * 2048 + 255) / 256, 256>>>(W_ih, W_hh, b_ih, b_hh);
    // W_fc [512 x 30000] -> Bext [30080 x 1536]
    k_tsp_ext<<<dim3(940, 16), dim3(32, 8)>>>(W_fc, Bext, VV, NPAD);
    // We_att [512 x 512] -> Wext [512 x 1536]
    k_tsp_ext<<<dim3(16, 16), dim3(32, 8)>>>(We_att, Wext, 512, 512);
    // feats -> Aext
    k_cvt_ext<<<(12544 * 512 + 255) / 256, 256>>>(encoder_feats, Aext, 12544 * 512);
    // enc_proj = feats @ We_att + be
    mma_gemm<0><<<dim3(4, 98), 256, SMEM>>>(Aext, Wext, enc_proj_ptr, be_att, 512, 12544, 512);

    // recurrence
    for (int t = 1; t < TT; t++) {
        int tm1 = t - 1;
        k_step1<<<1024, 256>>>(captions, emb_table, Wd_att, bd_att, W_beta, b_beta, tm1);
        k_att<<<64 * 25, 256>>>(wf_att, bf_att);
        k_softmax_ctx<<<dim3(BATCH, 2), 256>>>(encoder_feats);
        gemm_gates<<<dim3(16, 1, 8), 256>>>(x_ptr, wcat_ptr, gates_ptr, 2048, 1536, 192);
        k_lstm<<<128, 256>>>(tm1);
    }

    // H -> Aext (1920 rows), vocab projection
    k_cvt_ext<<<(1920 * 512 + 255) / 256, 256>>>(H_ptr, Aext, 1920 * 512);
    mma_gemm<2><<<dim3(NPAD / 128, 15), 256, SMEM>>>(Aext, Bext, out, b_fc,
                                                     VV, (TT - 1) * BATCH, VV);
}

// round 10
// speedup vs baseline: 1.6861x; 1.0880x over previous
#include <cuda_runtime.h>
#include <cuda_bf16.h>
#include <math.h>
#include <stdint.h>

// Problem dims
#define BATCH 64
#define PP    196
#define TT    30
#define VV    30000
#define NPAD  30080
#define KEXT  1536      // 3 x 512 (hi*hi + hi*lo + lo*hi)

// ---------------- device scratch ----------------
__device__ float g_enc_proj[BATCH * PP * 512];
__device__ float g_h[BATCH * 512];
__device__ float g_c[BATCH * 512];
__device__ float g_hgate[BATCH * 1024];
__device__ float g_scores[BATCH * PP];
__device__ float g_x[BATCH * 1536];
__device__ float g_gates[BATCH * 2048];
__device__ float g_Wcat[1536 * 2048];
__device__ float g_bias4[2048];
__device__ float g_gpre[1920 * 2048];            // precomputed emb@W_ih + bias, [t*64+b][n]
__device__ float g_H[TT * BATCH * 512];

__device__ __nv_bfloat16 g_Aext[12544 * KEXT];   // feats ext; reused for H ext
__device__ __nv_bfloat16 g_Bext[NPAD * KEXT];    // W_fc^T ext
__device__ __nv_bfloat16 g_Wext[512 * KEXT];     // We_att^T ext
__device__ __nv_bfloat16 g_Wihext[2048 * KEXT];  // W_ih[0:512]^T ext
__device__ __nv_bfloat16 g_Eext[1920 * KEXT];    // gathered emb ext

__device__ __forceinline__ float sigf(float x) { return 1.f / (1.f + expf(-x)); }
__device__ __forceinline__ float tanh_a(float x) {
    float y; asm("tanh.approx.f32 %0, %1;" : "=f"(y) : "f"(x)); return y;
}
__device__ __forceinline__ uint32_t smem_u32(const void* p) {
    uint32_t a;
    asm("{ .reg .u64 t; cvta.to.shared.u64 t, %1; cvt.u32.u64 %0, t; }" : "=r"(a) : "l"(p));
    return a;
}

// ---------------- mma.sync bf16 GEMM: C[M x N] = Aext[M x 1536] * Bext[N x 1536]^T ----------------
// EPI 0: C row-major [M x Nld] + bias. EPI 1: fp32 C row-major Nld + bias.
// EPI 2: vocab scatter + bias (m on blockIdx.x so m varies fastest -> B stays L2-resident).

#define NSTAGE (KEXT / 64)   // 24

__device__ __forceinline__ void ldm4(uint32_t* r, uint32_t addr) {
    asm volatile("ldmatrix.sync.aligned.m8n8.x4.shared.b16 {%0,%1,%2,%3}, [%4];"
        : "=r"(r[0]), "=r"(r[1]), "=r"(r[2]), "=r"(r[3]) : "r"(addr));
}
__device__ __forceinline__ void mma16816(float* c, const uint32_t* a, uint32_t b0, uint32_t b1) {
    asm volatile("mma.sync.aligned.m16n8k16.row.col.f32.bf16.bf16.f32 "
        "{%0,%1,%2,%3}, {%4,%5,%6,%7}, {%8,%9}, {%0,%1,%2,%3};"
        : "+f"(c[0]), "+f"(c[1]), "+f"(c[2]), "+f"(c[3])
        : "r"(a[0]), "r"(a[1]), "r"(a[2]), "r"(a[3]), "r"(b0), "r"(b1));
}
#define CPA(saddr, gaddr) \
    asm volatile("cp.async.cg.shared.global [%0], [%1], 16;" :: "r"(saddr), "l"(gaddr))
#define CPA_COMMIT() asm volatile("cp.async.commit_group;")
#define CPA_WAIT0()  asm volatile("cp.async.wait_group 0;")

template <int EPI>
__global__ void __launch_bounds__(256) mma_gemm(
    const __nv_bfloat16* __restrict__ Aext, const __nv_bfloat16* __restrict__ Bext,
    float* __restrict__ C, const float* __restrict__ bias,
    int Nld, int Mreal, int Nreal)
{
    extern __shared__ char sm[];
    const uint32_t sb = smem_u32(sm);
    const int tid = threadIdx.x;
    const int m0 = (EPI == 2 ? blockIdx.x : blockIdx.y) * 128;
    const int n0 = (EPI == 2 ? blockIdx.y : blockIdx.x) * 128;

    const __nv_bfloat16* Ag = Aext + (long)m0 * KEXT;
    const __nv_bfloat16* Bg = Bext + (long)n0 * KEXT;

    const int wid = tid >> 5, lane = tid & 31;
    const int wm = wid & 3, wn = wid >> 2;
    const int g = lane >> 3, r = lane & 7;
    const int lrow = (g & 1) * 8 + r;
    const uint32_t lkb = (g >> 1) * 16;
    const uint32_t xorp = (uint32_t)(r << 4);

    uint32_t aoff[2], boff[4];
#pragma unroll
    for (int mt = 0; mt < 2; mt++) aoff[mt] = (uint32_t)((wm * 32 + mt * 16 + lrow) * 128);
#pragma unroll
    for (int bt = 0; bt < 4; bt++) boff[bt] = (uint32_t)(16384 + (wn * 64 + bt * 16 + lrow) * 128);

    float acc[2][8][4];
#pragma unroll
    for (int i = 0; i < 2; i++)
#pragma unroll
        for (int j = 0; j < 8; j++)
#pragma unroll
            for (int q = 0; q < 4; q++) acc[i][j][q] = 0.f;

    {
#pragma unroll
        for (int i = 0; i < 4; i++) {
            int idx = i * 256 + tid;
            int row = idx >> 3, c = idx & 7;
            uint32_t so = (uint32_t)(row * 128 + ((c * 16) ^ ((row & 7) << 4)));
            CPA(sb + so, Ag + (long)row * KEXT + c * 8);
            CPA(sb + 16384 + so, Bg + (long)row * KEXT + c * 8);
        }
        CPA_COMMIT();
    }

    for (int s = 0; s < NSTAGE; s++) {
        CPA_WAIT0();
        __syncthreads();
        if (s + 1 < NSTAGE) {
            const uint32_t dstb = sb + ((s + 1) & 1) * 32768;
            const long kb = (long)(s + 1) * 64;
#pragma unroll
            for (int i = 0; i < 4; i++) {
                int idx = i * 256 + tid;
                int row = idx >> 3, c = idx & 7;
                uint32_t so = (uint32_t)(row * 128 + ((c * 16) ^ ((row & 7) << 4)));
                CPA(dstb + so, Ag + (long)row * KEXT + kb + c * 8);
                CPA(dstb + 16384 + so, Bg + (long)row * KEXT + kb + c * 8);
            }
            CPA_COMMIT();
        }

        const uint32_t sbase = sb + (s & 1) * 32768;
#pragma unroll
        for (int kk = 0; kk < 4; kk++) {
            const uint32_t kb = (uint32_t)(kk * 32 + lkb) ^ xorp;
            uint32_t a0[4], a1[4];
            ldm4(a0, sbase + aoff[0] + kb);
            ldm4(a1, sbase + aoff[1] + kb);
#pragma unroll
            for (int bt = 0; bt < 4; bt++) {
                uint32_t bm[4];
                ldm4(bm, sbase + boff[bt] + kb);
                mma16816(acc[0][2 * bt],     a0, bm[0], bm[2]);
                mma16816(acc[1][2 * bt],     a1, bm[0], bm[2]);
                mma16816(acc[0][2 * bt + 1], a0, bm[1], bm[3]);
                mma16816(acc[1][2 * bt + 1], a1, bm[1], bm[3]);
            }
        }
        __syncthreads();
    }

    // epilogue
    const int crow0 = lane >> 2;
    const int ccol = (lane & 3) * 2;
#pragma unroll
    for (int mt = 0; mt < 2; mt++) {
#pragma unroll
        for (int h = 0; h < 2; h++) {
            const int m = m0 + wm * 32 + mt * 16 + crow0 + h * 8;
            if (EPI == 2) {
                if (m < Mreal) {
                    int t = (m >> 6) + 1;
                    int b = m & 63;
                    float* crow = C + (long)b * (TT * VV) + (long)t * VV;
#pragma unroll
                    for (int nt = 0; nt < 8; nt++) {
                        const int n = n0 + wn * 64 + nt * 8 + ccol;
                        if (n < Nreal) {
                            float2 o;
                            o.x = acc[mt][nt][h * 2 + 0] + bias[n];
                            o.y = acc[mt][nt][h * 2 + 1] + bias[n + 1];
                            *reinterpret_cast<float2*>(crow + n) = o;
                        }
                    }
                }
            } else {
                float* crow = C + (long)m * Nld;
#pragma unroll
                for (int nt = 0; nt < 8; nt++) {
                    const int n = n0 + wn * 64 + nt * 8 + ccol;
                    float2 o;
                    o.x = acc[mt][nt][h * 2 + 0] + bias[n];
                    o.y = acc[mt][nt][h * 2 + 1] + bias[n + 1];
                    *reinterpret_cast<float2*>(crow + n) = o;
                }
            }
        }
    }
}

// ---------------- conversion kernels ----------------
__global__ void k_cvt_ext(const float* __restrict__ src, __nv_bfloat16* __restrict__ dst, int n) {
    int i = blockIdx.x * 256 + threadIdx.x;
    if (i < n) {
        int row = i >> 9, k = i & 511;
        float x = src[i];
        __nv_bfloat16 h = __float2bfloat16(x);
        __nv_bfloat16 l = __float2bfloat16(x - __bfloat162float(h));
        __nv_bfloat16* d = dst + (long)row * KEXT + k;
        d[0] = h; d[512] = h; d[1024] = l;
    }
}

// gather teacher-forced embeddings for all steps: row r = t*64+b (t=0..28)
__global__ void k_gather_emb(const int* __restrict__ captions, const float* __restrict__ emb) {
    int i = blockIdx.x * 256 + threadIdx.x;
    if (i < 1856 * 512) {
        int rrow = i >> 9, d = i & 511;
        int t = rrow >> 6, b = rrow & 63;
        int tok = captions[b * TT + t];
        float x = emb[(long)tok * 512 + d];
        __nv_bfloat16 h = __float2bfloat16(x);
        __nv_bfloat16 l = __float2bfloat16(x - __bfloat162float(h));
        __nv_bfloat16* dd = g_Eext + (long)rrow * KEXT + d;
        dd[0] = h; dd[512] = h; dd[1024] = l;
    }
}

__global__ void k_tsp_ext(const float* __restrict__ src, __nv_bfloat16* __restrict__ dst,
                          int N, int Npad) {
    __shared__ float t[32][33];
    int n0 = blockIdx.x * 32, k0 = blockIdx.y * 32;
    int tx = threadIdx.x, ty = threadIdx.y;
#pragma unroll
    for (int i = 0; i < 32; i += 8) {
        int k = k0 + ty + i, n = n0 + tx;
        t[ty + i][tx] = (n < N) ? src[(long)k * N + n] : 0.f;
    }
    __syncthreads();
#pragma unroll
    for (int i = 0; i < 32; i += 8) {
        int n = n0 + ty + i, k = k0 + tx;
        if (n < Npad) {
            float x = t[tx][ty + i];
            __nv_bfloat16 h = __float2bfloat16(x);
            __nv_bfloat16 l = __float2bfloat16(x - __bfloat162float(h));
            __nv_bfloat16* d = dst + (long)n * KEXT + k;
            d[0] = h; d[512] = l; d[1024] = h;
        }
    }
}

// ---------------- packed f32x2 SIMT GEMM (gates, K=1024 over [ctx|h]) ----------------
__device__ __forceinline__ unsigned long long pack2(float x) {
    unsigned long long r;
    asm("mov.b64 %0, {%1, %1};" : "=l"(r) : "f"(x));
    return r;
}
__device__ __forceinline__ void fma2(unsigned long long& d, unsigned long long a, unsigned long long b) {
    asm("fma.rn.f32x2 %0, %1, %2, %0;" : "+l"(d) : "l"(a), "l"(b));
}
__device__ __forceinline__ float2 unpack2(unsigned long long v) {
    float2 r;
    asm("mov.b64 {%0, %1}, %2;" : "=f"(r.x), "=f"(r.y) : "l"(v));
    return r;
}

__global__ void __launch_bounds__(256) gemm_gates(
    const float* __restrict__ A, const float* __restrict__ B,
    float* __restrict__ C, int N, int lda, int kLen)
{
    __shared__ float As[2][16][64];
    __shared__ float Bs[2][16][128];

    const int tid = threadIdx.x;
    const int n0 = blockIdx.x * 128;
    const int kStart = blockIdx.z * kLen;
    const int tn = (tid & 15) * 8;
    const int tm = (tid >> 4) * 4;
    const int am = tid >> 2, ak = (tid & 3) * 4;
    const int bk = tid >> 4, bn = (tid & 15) * 8;

    const float* Aptr = A + (long)am * lda + kStart + ak;
    const float* Bptr = B + (long)(kStart + bk) * N + n0 + bn;

    unsigned long long acc[4][4];
#pragma unroll
    for (int i = 0; i < 4; i++) acc[i][0] = acc[i][1] = acc[i][2] = acc[i][3] = 0ull;

    const int nb = kLen / 16;
    float4 ar0, br0, br1;
    ar0 = *reinterpret_cast<const float4*>(Aptr);
    br0 = *reinterpret_cast<const float4*>(Bptr);
    br1 = *reinterpret_cast<const float4*>(Bptr + 4);
    As[0][ak + 0][am] = ar0.x; As[0][ak + 1][am] = ar0.y;
    As[0][ak + 2][am] = ar0.z; As[0][ak + 3][am] = ar0.w;
    *reinterpret_cast<float4*>(&Bs[0][bk][bn]) = br0;
    *reinterpret_cast<float4*>(&Bs[0][bk][bn + 4]) = br1;
    __syncthreads();

    for (int ib = 0; ib < nb; ib++) {
        const int cur = ib & 1;
        const bool more = (ib + 1) < nb;
        if (more) {
            ar0 = *reinterpret_cast<const float4*>(Aptr + (ib + 1) * 16);
            const float* bp = Bptr + (long)((ib + 1) * 16) * N;
            br0 = *reinterpret_cast<const float4*>(bp);
            br1 = *reinterpret_cast<const float4*>(bp + 4);
        }
#pragma unroll
        for (int kk = 0; kk < 16; kk++) {
            unsigned long long ad[4];
            float4 af = *reinterpret_cast<const float4*>(&As[cur][kk][tm]);
            ad[0] = pack2(af.x); ad[1] = pack2(af.y); ad[2] = pack2(af.z); ad[3] = pack2(af.w);
            ulonglong2 bv0 = *reinterpret_cast<const ulonglong2*>(&Bs[cur][kk][tn]);
            ulonglong2 bv1 = *reinterpret_cast<const ulonglong2*>(&Bs[cur][kk][tn + 4]);
#pragma unroll
            for (int i = 0; i < 4; i++) {
                fma2(acc[i][0], ad[i], bv0.x);
                fma2(acc[i][1], ad[i], bv0.y);
                fma2(acc[i][2], ad[i], bv1.x);
                fma2(acc[i][3], ad[i], bv1.y);
            }
        }
        if (more) {
            const int nxt = cur ^ 1;
            As[nxt][ak + 0][am] = ar0.x; As[nxt][ak + 1][am] = ar0.y;
            As[nxt][ak + 2][am] = ar0.z; As[nxt][ak + 3][am] = ar0.w;
            *reinterpret_cast<float4*>(&Bs[nxt][bk][bn]) = br0;
            *reinterpret_cast<float4*>(&Bs[nxt][bk][bn + 4]) = br1;
        }
        __syncthreads();
    }

#pragma unroll
    for (int i = 0; i < 4; i++) {
        float* crow = C + (long)(tm + i) * N;
        float2 v[4];
        v[0] = unpack2(acc[i][0]); v[1] = unpack2(acc[i][1]);
        v[2] = unpack2(acc[i][2]); v[3] = unpack2(acc[i][3]);
#pragma unroll
        for (int j = 0; j < 4; j++) {
            int gn = n0 + tn + 2 * j;
            atomicAdd(crow + gn, v[j].x);
            atomicAdd(crow + gn + 1, v[j].y);
        }
    }
}

// ---------------- small kernels ----------------
__global__ void k_zero_t0(float* __restrict__ out) {
    int idx = blockIdx.x * 256 + threadIdx.x;
    if (idx < BATCH * VV) {
        int b = idx / VV, v = idx - b * VV;
        out[(long)b * (TT * VV) + v] = 0.f;
    }
}

__global__ void k_init_hc(const float* __restrict__ pooled,
                          const float* __restrict__ Wh, const float* __restrict__ bh,
                          const float* __restrict__ Wc, const float* __restrict__ bc) {
    int b = blockIdx.y;
    int j = blockIdx.x * 256 + threadIdx.x;
    __shared__ float pr[512];
    pr[threadIdx.x] = pooled[b * 512 + threadIdx.x];
    pr[threadIdx.x + 256] = pooled[b * 512 + threadIdx.x + 256];
    __syncthreads();
    float a0 = 0, a1 = 0, a2 = 0, a3 = 0;
    const float* W = (j < 512) ? (Wh + j) : (Wc + j - 512);
    for (int k = 0; k < 512; k += 4) {
        a0 += pr[k] * W[k * 512];
        a1 += pr[k + 1] * W[(k + 1) * 512];
        a2 += pr[k + 2] * W[(k + 2) * 512];
        a3 += pr[k + 3] * W[(k + 3) * 512];
    }
    float s = (a0 + a1) + (a2 + a3);
    if (j < 512) g_h[b * 512 + j] = tanhf(s + bh[j]);
    else         g_c[b * 512 + (j - 512)] = tanhf(s + bc[j - 512]);
}

__global__ void k_wcat(const float* __restrict__ Wih, const float* __restrict__ Whh,
                       const float* __restrict__ bih, const float* __restrict__ bhh) {
    int idx = blockIdx.x * 256 + threadIdx.x;
    if (idx < 1536 * 2048) {
        int k = idx >> 11, n = idx & 2047;
        g_Wcat[idx] = (k < 1024) ? Wih[idx] : Whh[(k - 1024) * 2048 + n];
    }
    if (idx < 2048) g_bias4[idx] = bih[idx] + bhh[idx];
}

// per step: dec_proj/gate (blocks 0..255); h->x copy + gates init from gpre (blocks 256..)
__global__ void k_step1(const float* __restrict__ Wd, const float* __restrict__ bd,
                        const float* __restrict__ Wb, const float* __restrict__ bb, int tm1) {
    int blk = blockIdx.x;
    if (blk < 256) {
        int b = blk >> 2;
        int j = (blk & 3) * 256 + threadIdx.x;
        __shared__ float hr[512];
        hr[threadIdx.x] = g_h[b * 512 + threadIdx.x];
        hr[threadIdx.x + 256] = g_h[b * 512 + threadIdx.x + 256];
        __syncthreads();
        float a0 = 0, a1 = 0, a2 = 0, a3 = 0;
        const float* W = (j < 512) ? (Wd + j) : (Wb + j - 512);
        for (int k = 0; k < 512; k += 4) {
            a0 += hr[k] * W[k * 512];
            a1 += hr[k + 1] * W[(k + 1) * 512];
            a2 += hr[k + 2] * W[(k + 2) * 512];
            a3 += hr[k + 3] * W[(k + 3) * 512];
        }
        float s = (a0 + a1) + (a2 + a3);
        if (j < 512) g_hgate[b * 1024 + j] = s + bd[j];
        else         g_hgate[b * 1024 + j] = sigf(s + bb[j - 512]);
    } else {
        int idx = (blk - 256) * 256 + threadIdx.x;   // < 163840
        if (idx < 32768) {
            int b = idx >> 9, k = idx & 511;
            g_x[b * 1536 + 1024 + k] = g_h[idx];
        } else {
            int rr = idx - 32768;                    // < 131072
            g_gates[rr] = g_gpre[(long)tm1 * 131072 + rr];
        }
    }
}

__global__ void k_att(const float* __restrict__ wf, const float* __restrict__ bf) {
    int b = blockIdx.x / 25;
    int pc = blockIdx.x % 25;
    __shared__ float dp[512], wfs[512];
    dp[threadIdx.x] = g_hgate[b * 1024 + threadIdx.x];
    dp[threadIdx.x + 256] = g_hgate[b * 1024 + threadIdx.x + 256];
    wfs[threadIdx.x] = wf[threadIdx.x];
    wfs[threadIdx.x + 256] = wf[threadIdx.x + 256];
    __syncthreads();
    int p = pc * 8 + (threadIdx.x >> 5);
    int lane = threadIdx.x & 31;
    if (p < PP) {
        const float* ep = g_enc_proj + ((long)(b * PP + p)) * 512;
        float acc = 0.f;
#pragma unroll
        for (int i = 0; i < 16; i++) {
            int a = i * 32 + lane;
            acc += tanh_a(ep[a] + dp[a]) * wfs[a];
        }
#pragma unroll
        for (int off = 16; off; off >>= 1) acc += __shfl_down_sync(0xffffffffu, acc, off);
        if (lane == 0) g_scores[b * PP + p] = acc + bf[0];
    }
}

__global__ void k_softmax_ctx(const float* __restrict__ feats) {
    int b = blockIdx.x;
    int tid = threadIdx.x;
    __shared__ float sc[256];
    __shared__ float red[256];
    float v = (tid < PP) ? g_scores[b * PP + tid] : -1e30f;
    red[tid] = v;
    __syncthreads();
    for (int s = 128; s > 0; s >>= 1) {
        if (tid < s) red[tid] = fmaxf(red[tid], red[tid + s]);
        __syncthreads();
    }
    float mx = red[0];
    __syncthreads();
    float e = (tid < PP) ? expf(v - mx) : 0.f;
    red[tid] = e;
    __syncthreads();
    for (int s = 128; s > 0; s >>= 1) {
        if (tid < s) red[tid] += red[tid + s];
        __syncthreads();
    }
    sc[tid] = e / red[0];
    __syncthreads();

    int d = blockIdx.y * 256 + tid;
    const float* fp = feats + (long)b * PP * 512 + d;
    float acc = 0.f;
#pragma unroll 4
    for (int p = 0; p < PP; p++) acc += sc[p] * fp[p * 512];
    g_x[b * 1536 + 512 + d] = acc * g_hgate[b * 1024 + 512 + d];
}

__global__ void k_lstm(int tm1) {
    int idx = blockIdx.x * 256 + threadIdx.x;
    int b = idx >> 9, d = idx & 511;
    const float* gg = g_gates + b * 2048;
    float ig = sigf(gg[d]);
    float fg = sigf(gg[512 + d]);
    float gv = tanhf(gg[1024 + d]);
    float og = sigf(gg[1536 + d]);
    float c2 = fg * g_c[idx] + ig * gv;
    float h2 = og * tanhf(c2);
    g_c[idx] = c2;
    g_h[idx] = h2;
    g_H[((long)tm1 * BATCH + b) * 512 + d] = h2;
}

// ---------------- launcher ----------------
extern "C" void kernel_launch(void* const* d_in, const int* in_sizes, int n_in,
                              void* d_out, int out_size) {
    const float* encoder_feats  = (const float*)d_in[0];
    const float* encoder_pooled = (const float*)d_in[1];
    const int*   captions       = (const int*)d_in[2];
    const float* We_att  = (const float*)d_in[3];
    const float* be_att  = (const float*)d_in[4];
    const float* Wd_att  = (const float*)d_in[5];
    const float* bd_att  = (const float*)d_in[6];
    const float* wf_att  = (const float*)d_in[7];
    const float* bf_att  = (const float*)d_in[8];
    const float* emb_table = (const float*)d_in[9];
    const float* W_ih = (const float*)d_in[10];
    const float* W_hh = (const float*)d_in[11];
    const float* b_ih = (const float*)d_in[12];
    const float* b_hh = (const float*)d_in[13];
    const float* W_init_h = (const float*)d_in[14];
    const float* b_init_h = (const float*)d_in[15];
    const float* W_init_c = (const float*)d_in[16];
    const float* b_init_c = (const float*)d_in[17];
    const float* W_fc  = (const float*)d_in[18];
    const float* b_fc  = (const float*)d_in[19];
    const float* W_beta = (const float*)d_in[20];
    const float* b_beta = (const float*)d_in[21];
    float* out = (float*)d_out;

    void* p;
    cudaGetSymbolAddress(&p, g_enc_proj); float* enc_proj_ptr = (float*)p;
    cudaGetSymbolAddress(&p, g_x);        float* x_ptr = (float*)p;
    cudaGetSymbolAddress(&p, g_Wcat);     float* wcat_ptr = (float*)p;
    cudaGetSymbolAddress(&p, g_gates);    float* gates_ptr = (float*)p;
    cudaGetSymbolAddress(&p, g_bias4);    float* bias4_ptr = (float*)p;
    cudaGetSymbolAddress(&p, g_gpre);     float* gpre_ptr = (float*)p;
    cudaGetSymbolAddress(&p, g_H);        float* H_ptr = (float*)p;
    cudaGetSymbolAddress(&p, g_Aext);     __nv_bfloat16* Aext = (__nv_bfloat16*)p;
    cudaGetSymbolAddress(&p, g_Bext);     __nv_bfloat16* Bext = (__nv_bfloat16*)p;
    cudaGetSymbolAddress(&p, g_Wext);     __nv_bfloat16* Wext = (__nv_bfloat16*)p;
    cudaGetSymbolAddress(&p, g_Wihext);   __nv_bfloat16* Wihext = (__nv_bfloat16*)p;
    cudaGetSymbolAddress(&p, g_Eext);     __nv_bfloat16* Eext = (__nv_bfloat16*)p;

    const int SMEM = 64 * 1024;
    cudaFuncSetAttribute(mma_gemm<0>, cudaFuncAttributeMaxDynamicSharedMemorySize, SMEM);
    cudaFuncSetAttribute(mma_gemm<1>, cudaFuncAttributeMaxDynamicSharedMemorySize, SMEM);
    cudaFuncSetAttribute(mma_gemm<2>, cudaFuncAttributeMaxDynamicSharedMemorySize, SMEM);

    // prologue
    k_zero_t0<<<(BATCH * VV + 255) / 256, 256>>>(out);
    k_init_hc<<<dim3(4, BATCH), 256>>>(encoder_pooled, W_init_h, b_init_h, W_init_c, b_init_c);
    k_wcat<<<(1536 * 2048 + 255) / 256, 256>>>(W_ih, W_hh, b_ih, b_hh);
    // W_fc [512 x 30000] -> Bext [30080 x 1536]
    k_tsp_ext<<<dim3(940, 16), dim3(32, 8)>>>(W_fc, Bext, VV, NPAD);
    // We_att [512 x 512] -> Wext
    k_tsp_ext<<<dim3(16, 16), dim3(32, 8)>>>(We_att, Wext, 512, 512);
    // W_ih[0:512] [512 x 2048] -> Wihext [2048 x 1536]
    k_tsp_ext<<<dim3(64, 16), dim3(32, 8)>>>(W_ih, Wihext, 2048, 2048);
    // feats -> Aext
    k_cvt_ext<<<(12544 * 512 + 255) / 256, 256>>>(encoder_feats, Aext, 12544 * 512);
    // gather all teacher-forced embeddings -> Eext
    k_gather_emb<<<(1856 * 512 + 255) / 256, 256>>>(captions, emb_table);
    // enc_proj = feats @ We_att + be
    mma_gemm<0><<<dim3(4, 98), 256, SMEM>>>(Aext, Wext, enc_proj_ptr, be_att, 512, 12544, 512);
    // gates_pre = emb @ W_ih[0:512] + (b_ih + b_hh) : [1920 x 2048]
    mma_gemm<1><<<dim3(16, 15), 256, SMEM>>>(Eext, Wihext, gpre_ptr, bias4_ptr, 2048, 1920, 2048);

    // recurrence (R4 structure, 5 launches/step; gates GEMM K=1024 over [ctx|h])
    for (int t = 1; t < TT; t++) {
        int tm1 = t - 1;
        k_step1<<<896, 256>>>(Wd_att, bd_att, W_beta, b_beta, tm1);
        k_att<<<64 * 25, 256>>>(wf_att, bf_att);
        k_softmax_ctx<<<dim3(BATCH, 2), 256>>>(encoder_feats);
        gemm_gates<<<dim3(16, 1, 8), 256>>>(x_ptr + 512, wcat_ptr + 512 * 2048, gates_ptr,
                                            2048, 1536, 128);
        k_lstm<<<128, 256>>>(tm1);
    }

    // H -> Aext (1920 rows), vocab projection (m varies fastest: B L2-resident)
    k_cvt_ext<<<(1920 * 512 + 255) / 256, 256>>>(H_ptr, Aext, 1920 * 512);
    mma_gemm<2><<<dim3(15, NPAD / 128), 256, SMEM>>>(Aext, Bext, out, b_fc,
                                                     VV, (TT - 1) * BATCH, VV);
}